// round 15
// baseline (speedup 1.0000x reference)
#include <cuda_runtime.h>
#include <cstdint>
#include <cstddef>

// ---------------- problem constants ----------------
#define BATCH   8
#define T_ENC   1024
#define T_DEC   100
#define DMODEL  512
#define NHEAD   8
#define DHEAD   64
#define DFF     2048
#define M_ENC   (BATCH * T_ENC)   // 8192
#define M_DEC   (BATCH * T_DEC)   // 800
#define BHT     (BATCH * NHEAD)   // 64
#define NQKV    1536
#define NKV2    2048              // both decoder layers' K|V fused along N

// ---------------- fused tf32 weights, TRANSPOSED [N][K] ----------------
__device__ uint32_t w_eqkv[2 * NQKV * DMODEL];
__device__ uint32_t w_ew1 [2 * DFF * DMODEL];
__device__ uint32_t w_ew2 [2 * DMODEL * DFF];
__device__ uint32_t w_dqkv1[2 * NQKV * DMODEL];
__device__ uint32_t w_dq2 [2 * DMODEL * DMODEL];
__device__ uint32_t w_dkv2[NKV2 * DMODEL];
__device__ uint32_t w_dw1 [2 * DFF * DMODEL];
__device__ uint32_t w_dw2 [2 * DMODEL * DFF];

// ---------------- activations / scratch ----------------
__device__ uint32_t g_qkv [M_ENC * NQKV];        // enc Q|K (tf32); V region unused
__device__ float    g_qkvd[M_DEC * NQKV];        // dec self QKV (fp32 exact)
__device__ uint32_t g_kv  [M_ENC * NKV2];        // dec cross K both layers; V regions unused
__device__ uint32_t g_vtE [BHT * DHEAD * T_ENC]; // enc V, d-major [bh][64][1024]
__device__ uint32_t g_vtD [2 * BHT * DHEAD * T_ENC]; // dec cross V, per layer
__device__ uint32_t g_qx  [M_DEC * DMODEL];
__device__ uint32_t g_h   [M_ENC * DFF];
__device__ uint32_t g_xtf [M_ENC * DMODEL];
__device__ uint32_t g_x1tf[M_ENC * DMODEL];
__device__ uint32_t g_ytf [M_DEC * DMODEL];
__device__ uint32_t g_y1tf[M_DEC * DMODEL];
__device__ uint32_t g_y2tf[M_DEC * DMODEL];
__device__ float g_att [M_ENC * DMODEL];
__device__ float g_x1  [M_ENC * DMODEL];
__device__ float g_x   [M_ENC * DMODEL];
__device__ float g_y1  [M_DEC * DMODEL];
__device__ float g_y2  [M_DEC * DMODEL];
__device__ float g_y   [M_DEC * DMODEL];

__device__ __forceinline__ uint32_t f2tf32(float x) {
    uint32_t t;
    asm("cvt.rna.tf32.f32 %0, %1;" : "=r"(t) : "f"(x));
    return t;
}

__device__ __forceinline__ void mma8(float* c, const uint32_t* a, uint32_t b0, uint32_t b1) {
    asm volatile(
        "mma.sync.aligned.m16n8k8.row.col.f32.tf32.tf32.f32 "
        "{%0,%1,%2,%3}, {%4,%5,%6,%7}, {%8,%9}, {%0,%1,%2,%3};"
        : "+f"(c[0]), "+f"(c[1]), "+f"(c[2]), "+f"(c[3])
        : "r"(a[0]), "r"(a[1]), "r"(a[2]), "r"(a[3]), "r"(b0), "r"(b1));
}

__device__ __forceinline__ void ldsm4(uint32_t& r0, uint32_t& r1, uint32_t& r2, uint32_t& r3,
                                      uint32_t addr) {
    asm volatile("ldmatrix.sync.aligned.m8n8.x4.shared.b16 {%0,%1,%2,%3}, [%4];"
                 : "=r"(r0), "=r"(r1), "=r"(r2), "=r"(r3) : "r"(addr));
}

__device__ __forceinline__ void cpasync16(uint32_t smem_dst, const void* gsrc, int bytes) {
    asm volatile("cp.async.ca.shared.global [%0], [%1], 16, %2;"
                 :: "r"(smem_dst), "l"(gsrc), "r"(bytes));
}

__device__ __forceinline__ uint4 cvt4(float4 v) {
    return make_uint4(f2tf32(v.x), f2tf32(v.y), f2tf32(v.z), f2tf32(v.w));
}

// ---------------- transpose-convert packing: src [K][N] fp32 -> dst [N][K] tf32 ----------------
struct TJob { const float* src; uint32_t* dst; int K; int N; float scale; };
struct TJobs { TJob j[26]; };

__global__ void tpack_kernel(TJobs jobs, int njobs) {
    const int job = blockIdx.z;
    if (job >= njobs) return;
    const TJob jb = jobs.j[job];
    const int nt = blockIdx.x << 5, kt = blockIdx.y << 5;
    if (nt >= jb.N || kt >= jb.K) return;
    __shared__ float tile[32][33];
    const int tx = threadIdx.x & 31, ty = threadIdx.x >> 5;
    #pragma unroll
    for (int i = 0; i < 4; i++) {
        int k = kt + ty + i * 8;
        tile[ty + i * 8][tx] = jb.src[(size_t)k * jb.N + nt + tx];
    }
    __syncthreads();
    #pragma unroll
    for (int i = 0; i < 4; i++) {
        int n = nt + ty + i * 8;
        jb.dst[(size_t)n * jb.K + kt + tx] = f2tf32(tile[tx][ty + i * 8] * jb.scale);
    }
}

// ---------------- plain conversion (x / y inputs) ----------------
struct ConvJob { const float4* src; uint4* dst; int n4; };
struct ConvJobs { ConvJob j[2]; };

__global__ void conv_multi_kernel(ConvJobs jobs, int njobs) {
    int seg = blockIdx.y;
    if (seg >= njobs) return;
    ConvJob jb = jobs.j[seg];
    for (int i = blockIdx.x * blockDim.x + threadIdx.x; i < jb.n4; i += gridDim.x * blockDim.x) {
        jb.dst[i] = cvt4(jb.src[i]);
    }
}

// ================= 3-stage cp.async tf32 GEMM (ldmatrix A+B; V-transpose epilogue) =================
// Reg-limited to 2 CTAs/SM, so the extra stage is occupancy-free; issue-before-wait
// keeps two K-tiles in flight.
#define GA_STRIDE 36
#define GA_STAGE  (128 * GA_STRIDE)
#define GB_STAGE  (128 * GA_STRIDE)
#define GEMM_SMEM ((3 * GA_STAGE + 3 * GB_STAGE) * 4)

template<int RELU, int TF32OUT>
__global__ __launch_bounds__(256)
void mma_gemm(const uint32_t* __restrict__ A, const uint32_t* __restrict__ B,
              const float* __restrict__ bias, void* __restrict__ Cv,
              int M, int N, int K, int vmode, uint32_t* __restrict__ vt)
{
    extern __shared__ uint32_t gsm[];
    uint32_t* Asf = gsm;
    uint32_t* Bsf = gsm + 3 * GA_STAGE;

    const int tid  = threadIdx.x;
    const int wid  = tid >> 5, lane = tid & 31;
    const int wm   = wid & 1, wn = wid >> 1;
    const int g    = lane >> 2, tig = lane & 3;
    const int m0   = blockIdx.y * 128, n0 = blockIdx.x * 128;

    const int lt = lane >> 3, lr = lane & 7;
    const int a_row = lr + ((lt & 1) << 3);
    const int a_col = (lt >> 1) << 2;
    const int b_row = lr + ((lt >> 1) << 3);
    const int b_col = (lt & 1) << 2;

    const uint32_t aBase = (uint32_t)__cvta_generic_to_shared(Asf);
    const uint32_t bBase = (uint32_t)__cvta_generic_to_shared(Bsf);

    float acc[4][4][4];
    #pragma unroll
    for (int i = 0; i < 4; i++)
        #pragma unroll
        for (int j = 0; j < 4; j++)
            #pragma unroll
            for (int c = 0; c < 4; c++) acc[i][j][c] = 0.f;

    auto issue = [&](int s, int k0) {
        #pragma unroll
        for (int i = 0; i < 4; i++) {
            int idx = tid + (i << 8);
            int r = idx >> 3, kk4 = (idx & 7) << 2;
            int m = m0 + r;
            const uint32_t* src = A + (size_t)(m < M ? m : 0) * K + k0 + kk4;
            cpasync16(aBase + (s * GA_STAGE + r * GA_STRIDE + kk4) * 4, src, (m < M) ? 16 : 0);
        }
        #pragma unroll
        for (int i = 0; i < 4; i++) {
            int idx = tid + (i << 8);
            int r = idx >> 3, kk4 = (idx & 7) << 2;
            const uint32_t* src = B + (size_t)(n0 + r) * K + k0 + kk4;
            cpasync16(bBase + (s * GB_STAGE + r * GA_STRIDE + kk4) * 4, src, 16);
        }
        asm volatile("cp.async.commit_group;");
    };

    const int nk = K >> 5;
    issue(0, 0);
    if (nk > 1) issue(1, 32);

    int s = 0;
    for (int kt = 0; kt < nk; kt++) {
        if (kt + 2 < nk) {
            int s2 = s + 2; if (s2 >= 3) s2 -= 3;
            issue(s2, (kt + 2) << 5);   // stage last read at iter kt-1 (end barrier protects)
            asm volatile("cp.async.wait_group 2;");
        } else if (kt + 1 < nk) {
            asm volatile("cp.async.wait_group 1;");
        } else {
            asm volatile("cp.async.wait_group 0;");
        }
        __syncthreads();

        const uint32_t aLane = aBase +
            (s * GA_STAGE + (wm * 64 + a_row) * GA_STRIDE + a_col) * 4;
        const uint32_t bLane = bBase +
            (s * GB_STAGE + (wn * 32 + b_row) * GA_STRIDE + b_col) * 4;
        #pragma unroll
        for (int ks = 0; ks < 32; ks += 8) {
            uint32_t af[4][4];
            #pragma unroll
            for (int mi = 0; mi < 4; mi++)
                ldsm4(af[mi][0], af[mi][1], af[mi][2], af[mi][3],
                      aLane + (mi * 16 * GA_STRIDE + ks) * 4);
            uint32_t bf[4][2];
            ldsm4(bf[0][0], bf[0][1], bf[1][0], bf[1][1], bLane + ks * 4);
            ldsm4(bf[2][0], bf[2][1], bf[3][0], bf[3][1],
                  bLane + (16 * GA_STRIDE + ks) * 4);
            #pragma unroll
            for (int mi = 0; mi < 4; mi++)
                #pragma unroll
                for (int ni = 0; ni < 4; ni++)
                    mma8(acc[mi][ni], af[mi], bf[ni][0], bf[ni][1]);
        }
        __syncthreads();
        if (++s >= 3) s -= 3;
    }

    // ---- epilogue ----
    bool vtile = false;
    int vrow0 = 0;
    if (TF32OUT && vmode) {
        if (vmode == 1 && n0 >= 1024) {
            vtile = true;
            vrow0 = (m0 >> 10) * 512 + (n0 - 1024);
        } else if (vmode == 2 && (n0 & 512)) {
            vtile = true;
            vrow0 = (n0 >> 10) * 4096 + (m0 >> 10) * 512 + ((n0 & 1023) - 512);
        }
    }

    if (!vtile) {
        #pragma unroll
        for (int mi = 0; mi < 4; mi++) {
            int mb = m0 + wm * 64 + mi * 16;
            #pragma unroll
            for (int ni = 0; ni < 4; ni++) {
                int nb = n0 + wn * 32 + ni * 8 + 2 * tig;
                #pragma unroll
                for (int half = 0; half < 2; half++) {
                    int m = mb + g + half * 8;
                    if (m < M) {
                        float v0 = acc[mi][ni][half * 2    ];
                        float v1 = acc[mi][ni][half * 2 + 1];
                        if (bias) { v0 += bias[nb]; v1 += bias[nb + 1]; }
                        if (RELU) { v0 = fmaxf(v0, 0.f); v1 = fmaxf(v1, 0.f); }
                        if (TF32OUT) {
                            *(uint2*)((uint32_t*)Cv + (size_t)m * N + nb) =
                                make_uint2(f2tf32(v0), f2tf32(v1));
                        } else {
                            *(float2*)((float*)Cv + (size_t)m * N + nb) = make_float2(v0, v1);
                        }
                    }
                }
            }
        }
    } else {
        uint32_t* st = gsm;   // 128 x 132 (<= GEMM smem)
        #pragma unroll
        for (int mi = 0; mi < 4; mi++) {
            int mloc = wm * 64 + mi * 16 + g;
            #pragma unroll
            for (int ni = 0; ni < 4; ni++) {
                int nloc = wn * 32 + ni * 8 + 2 * tig;
                st[(nloc    ) * 132 + mloc    ] = f2tf32(acc[mi][ni][0]);
                st[(nloc + 1) * 132 + mloc    ] = f2tf32(acc[mi][ni][1]);
                st[(nloc    ) * 132 + mloc + 8] = f2tf32(acc[mi][ni][2]);
                st[(nloc + 1) * 132 + mloc + 8] = f2tf32(acc[mi][ni][3]);
            }
        }
        __syncthreads();
        const int tok0 = m0 & 1023;
        #pragma unroll
        for (int it = 0; it < 16; it++) {
            int idx = tid + (it << 8);
            int r = idx >> 5, ch = (idx & 31) << 2;
            uint4 v = *(uint4*)&st[r * 132 + ch];
            *(uint4*)(vt + (size_t)(vrow0 + r) * 1024 + tok0 + ch) = v;
        }
    }
}

// ================= fused flash attention (non-causal, exact) — R12 proven =================
// 2-stage KV pipeline; Q hoisted to registers; P in registers via quad shuffles;
// V d-major. smem = KV double buffers only (70KB).
#define FQ_STRIDE 68
#define FKV_STAGE (64 * FQ_STRIDE)
#define FLASH_SMEM ((4 * FKV_STAGE) * 4)

__global__ __launch_bounds__(256, 2)
void flash_attn(const uint32_t* __restrict__ Qg, int ldq,
                const uint32_t* __restrict__ Kg, int ldkv,
                const uint32_t* __restrict__ Vt,
                float* __restrict__ Og, int Tq, int Tk)
{
    extern __shared__ uint32_t fsm[];
    uint32_t* Kraw = fsm;                    // 2 x [64][68]
    uint32_t* Vraw = fsm + 2 * FKV_STAGE;    // 2 x [64][68]

    const int bh = blockIdx.y;
    const int b = bh >> 3, h = bh & 7;
    const int q0 = blockIdx.x * 128;
    const int tid = threadIdx.x;
    const int wid = tid >> 5, lane = tid & 31;
    const int g = lane >> 2, tig = lane & 3;
    const int mr = wid * 16;

    const int lt = lane >> 3, lr = lane & 7;
    const int a_row = lr + ((lt & 1) << 3);
    const int a_col = (lt >> 1) << 2;
    const int k_row = lr + ((lt >> 1) << 3);
    const int k_col = (lt & 1) << 2;

    const uint32_t* qp = Qg + (size_t)b * Tq * ldq + h * DHEAD;
    const uint32_t* kp = Kg + (size_t)b * Tk * ldkv + h * DHEAD;
    const uint32_t* vp = Vt + (size_t)bh * 64 * Tk;

    const uint32_t kBase = (uint32_t)__cvta_generic_to_shared(Kraw);
    const uint32_t vBase = (uint32_t)__cvta_generic_to_shared(Vraw);

    // ---- stage Q (128 x 64) through the 128-row K+V buffer space, hoist to regs ----
    #pragma unroll
    for (int i = 0; i < 8; i++) {
        int idx = tid + (i << 8);
        int r = idx >> 4, d4 = (idx & 15) << 2;
        int q = q0 + r;
        cpasync16(kBase + (r * FQ_STRIDE + d4) * 4,
                  qp + (size_t)(q < Tq ? q : 0) * ldq + d4, 16);
    }
    asm volatile("cp.async.commit_group;");
    asm volatile("cp.async.wait_group 0;");
    __syncthreads();
    uint32_t qf[8][4];
    {
        const uint32_t qLane = kBase + ((mr + a_row) * FQ_STRIDE + a_col) * 4;
        #pragma unroll
        for (int j = 0; j < 8; j++)
            ldsm4(qf[j][0], qf[j][1], qf[j][2], qf[j][3], qLane + (j << 5));
    }
    __syncthreads();   // all warps done reading Q before KV overwrites the buffer

    auto issueKV = [&](int s, int kt) {
        #pragma unroll
        for (int i = 0; i < 4; i++) {
            int idx = tid + (i << 8);
            int r = idx >> 4, d4 = (idx & 15) << 2;
            cpasync16(kBase + (s * FKV_STAGE + r * FQ_STRIDE + d4) * 4,
                      kp + (size_t)(kt + r) * ldkv + d4, 16);
            cpasync16(vBase + (s * FKV_STAGE + r * FQ_STRIDE + d4) * 4,
                      vp + (size_t)r * Tk + kt + d4, 16);
        }
        asm volatile("cp.async.commit_group;");
    };

    issueKV(0, 0);

    float o[8][4];
    #pragma unroll
    for (int ni = 0; ni < 8; ni++)
        #pragma unroll
        for (int c = 0; c < 4; c++) o[ni][c] = 0.f;
    float m0 = -1e30f, m1 = -1e30f, l0 = 0.f, l1 = 0.f;

    const int srcA = (lane & ~3) | (tig >> 1);
    const int srcB = srcA + 2;
    const bool odd = tig & 1;

    const int nt = Tk >> 6;
    for (int kt = 0; kt < nt; kt++) {
        const int s = kt & 1;
        if (kt + 1 < nt) {
            issueKV(s ^ 1, (kt + 1) << 6);
            asm volatile("cp.async.wait_group 1;");
        } else {
            asm volatile("cp.async.wait_group 0;");
        }
        __syncthreads();

        const uint32_t kLane = kBase + (s * FKV_STAGE + k_row * FQ_STRIDE + k_col) * 4;
        const uint32_t vLane = vBase + (s * FKV_STAGE + k_row * FQ_STRIDE + k_col) * 4;

        // ---- S = Q @ K^T (Q from registers) ----
        float sfr[8][4];
        #pragma unroll
        for (int ni = 0; ni < 8; ni++)
            #pragma unroll
            for (int c = 0; c < 4; c++) sfr[ni][c] = 0.f;
        #pragma unroll
        for (int j = 0; j < 8; j++) {
            const int ks = j * 8;
            #pragma unroll
            for (int np = 0; np < 8; np += 2) {
                uint32_t b00, b01, b10, b11;
                ldsm4(b00, b01, b10, b11, kLane + (np * 8 * FQ_STRIDE + ks) * 4);
                mma8(sfr[np    ], qf[j], b00, b01);
                mma8(sfr[np + 1], qf[j], b10, b11);
            }
        }

        // ---- online softmax; tf32 P bits stored in-place in sfr ----
        float tmax0 = -1e30f, tmax1 = -1e30f;
        #pragma unroll
        for (int ni = 0; ni < 8; ni++) {
            tmax0 = fmaxf(tmax0, fmaxf(sfr[ni][0], sfr[ni][1]));
            tmax1 = fmaxf(tmax1, fmaxf(sfr[ni][2], sfr[ni][3]));
        }
        #pragma unroll
        for (int off = 1; off <= 2; off <<= 1) {
            tmax0 = fmaxf(tmax0, __shfl_xor_sync(0xffffffffu, tmax0, off));
            tmax1 = fmaxf(tmax1, __shfl_xor_sync(0xffffffffu, tmax1, off));
        }
        const float mn0 = fmaxf(m0, tmax0), mn1 = fmaxf(m1, tmax1);
        const float a0 = __expf(m0 - mn0), a1 = __expf(m1 - mn1);
        float rs0 = 0.f, rs1 = 0.f;
        #pragma unroll
        for (int ni = 0; ni < 8; ni++) {
            float p0 = __expf(sfr[ni][0] - mn0);
            float p1 = __expf(sfr[ni][1] - mn0);
            float p2 = __expf(sfr[ni][2] - mn1);
            float p3 = __expf(sfr[ni][3] - mn1);
            rs0 += p0 + p1; rs1 += p2 + p3;
            sfr[ni][0] = __uint_as_float(f2tf32(p0));
            sfr[ni][1] = __uint_as_float(f2tf32(p1));
            sfr[ni][2] = __uint_as_float(f2tf32(p2));
            sfr[ni][3] = __uint_as_float(f2tf32(p3));
        }
        #pragma unroll
        for (int off = 1; off <= 2; off <<= 1) {
            rs0 += __shfl_xor_sync(0xffffffffu, rs0, off);
            rs1 += __shfl_xor_sync(0xffffffffu, rs1, off);
        }
        l0 = l0 * a0 + rs0; l1 = l1 * a1 + rs1;
        m0 = mn0; m1 = mn1;
        #pragma unroll
        for (int ni = 0; ni < 8; ni++) {
            o[ni][0] *= a0; o[ni][1] *= a0;
            o[ni][2] *= a1; o[ni][3] *= a1;
        }

        // ---- O += P @ V : P c-frag -> a-frag via quad shuffles; V via ldmatrix ----
        #pragma unroll
        for (int j = 0; j < 8; j++) {
            uint32_t p0 = __float_as_uint(sfr[j][0]);
            uint32_t p1 = __float_as_uint(sfr[j][1]);
            uint32_t p2 = __float_as_uint(sfr[j][2]);
            uint32_t p3 = __float_as_uint(sfr[j][3]);
            uint32_t r0a = __shfl_sync(0xffffffffu, p0, srcA);
            uint32_t r1a = __shfl_sync(0xffffffffu, p1, srcA);
            uint32_t r2a = __shfl_sync(0xffffffffu, p2, srcA);
            uint32_t r3a = __shfl_sync(0xffffffffu, p3, srcA);
            uint32_t r0b = __shfl_sync(0xffffffffu, p0, srcB);
            uint32_t r1b = __shfl_sync(0xffffffffu, p1, srcB);
            uint32_t r2b = __shfl_sync(0xffffffffu, p2, srcB);
            uint32_t r3b = __shfl_sync(0xffffffffu, p3, srcB);
            uint32_t af[4];
            af[0] = odd ? r1a : r0a;
            af[1] = odd ? r3a : r2a;
            af[2] = odd ? r1b : r0b;
            af[3] = odd ? r3b : r2b;
            const int ks = j * 8;
            #pragma unroll
            for (int np = 0; np < 8; np += 2) {
                uint32_t b00, b01, b10, b11;
                ldsm4(b00, b01, b10, b11, vLane + (np * 8 * FQ_STRIDE + ks) * 4);
                mma8(o[np    ], af, b00, b01);
                mma8(o[np + 1], af, b10, b11);
            }
        }
        __syncthreads();
    }

    const float i0 = 1.f / l0, i1 = 1.f / l1;
    #pragma unroll
    for (int ni = 0; ni < 8; ni++) {
        int col = h * DHEAD + ni * 8 + 2 * tig;
        int r0 = q0 + mr + g, r1 = r0 + 8;
        if (r0 < Tq)
            *(float2*)(Og + (size_t)(b * Tq + r0) * DMODEL + col) =
                make_float2(o[ni][0] * i0, o[ni][1] * i0);
        if (r1 < Tq)
            *(float2*)(Og + (size_t)(b * Tq + r1) * DMODEL + col) =
                make_float2(o[ni][2] * i1, o[ni][3] * i1);
    }
}

// ================= fused decoder self-attention (exact fp32) =================
#define DS_STRIDE 68
#define DS_SSTRIDE 104
#define DEC_SMEM ((3 * T_DEC * DS_STRIDE + T_DEC * DS_SSTRIDE) * 4)

__global__ __launch_bounds__(256)
void dec_self_attn(const float* __restrict__ QKV, float* __restrict__ Og)
{
    extern __shared__ float dsm[];
    float* Qd = dsm;
    float* Kd = Qd + T_DEC * DS_STRIDE;
    float* Vd = Kd + T_DEC * DS_STRIDE;
    float* Sd = Vd + T_DEC * DS_STRIDE;

    const int bh = blockIdx.x;
    const int b = bh >> 3, h = bh & 7;
    const int tid = threadIdx.x;
    const int wid = tid >> 5, lane = tid & 31;

    const float* qp = QKV + (size_t)b * T_DEC * NQKV + h * DHEAD;
    const float* kp = qp + 512;
    const float* vp = qp + 1024;

    for (int idx = tid; idx < T_DEC * 16; idx += 256) {
        int r = idx >> 4, d4 = (idx & 15) << 2;
        *(float4*)&Qd[r * DS_STRIDE + d4] = *(const float4*)(qp + (size_t)r * NQKV + d4);
        *(float4*)&Kd[r * DS_STRIDE + d4] = *(const float4*)(kp + (size_t)r * NQKV + d4);
        *(float4*)&Vd[r * DS_STRIDE + d4] = *(const float4*)(vp + (size_t)r * NQKV + d4);
    }
    __syncthreads();

    for (int e = tid; e < T_DEC * T_DEC; e += 256) {
        int q = e / T_DEC, kk = e - q * T_DEC;
        const float* qr = &Qd[q * DS_STRIDE];
        const float* kr = &Kd[kk * DS_STRIDE];
        float acc = 0.f;
        #pragma unroll
        for (int d = 0; d < 64; d++) acc += qr[d] * kr[d];
        Sd[q * DS_SSTRIDE + kk] = acc * 0.125f;
    }
    __syncthreads();

    for (int q = wid; q < T_DEC; q += 8) {
        float* row = &Sd[q * DS_SSTRIDE];
        float r0 = (lane      < T_DEC) ? row[lane]      : -1e30f;
        float r1 = (lane + 32 < T_DEC) ? row[lane + 32] : -1e30f;
        float r2 = (lane + 64 < T_DEC) ? row[lane + 64] : -1e30f;
        float r3 = (lane + 96 < T_DEC) ? row[lane + 96] : -1e30f;
        float m = fmaxf(fmaxf(r0, r1), fmaxf(r2, r3));
        #pragma unroll
        for (int off = 16; off; off >>= 1) m = fmaxf(m, __shfl_xor_sync(0xffffffffu, m, off));
        float e0 = expf(r0 - m), e1 = expf(r1 - m), e2 = expf(r2 - m), e3 = expf(r3 - m);
        if (lane      >= T_DEC) e0 = 0.f;
        if (lane + 32 >= T_DEC) e1 = 0.f;
        if (lane + 64 >= T_DEC) e2 = 0.f;
        if (lane + 96 >= T_DEC) e3 = 0.f;
        float s = e0 + e1 + e2 + e3;
        #pragma unroll
        for (int off = 16; off; off >>= 1) s += __shfl_xor_sync(0xffffffffu, s, off);
        const float inv = 1.f / s;
        if (lane      < T_DEC) row[lane]      = (lane      > q) ? -1e10f : e0 * inv;
        if (lane + 32 < T_DEC) row[lane + 32] = (lane + 32 > q) ? -1e10f : e1 * inv;
        if (lane + 64 < T_DEC) row[lane + 64] = (lane + 64 > q) ? -1e10f : e2 * inv;
        if (lane + 96 < T_DEC) row[lane + 96] = (lane + 96 > q) ? -1e10f : e3 * inv;
    }
    __syncthreads();

    for (int e = tid; e < T_DEC * 64; e += 256) {
        int q = e >> 6, d = e & 63;
        const float* pr = &Sd[q * DS_SSTRIDE];
        float acc = 0.f;
        #pragma unroll 4
        for (int kk = 0; kk < T_DEC; kk++) acc += pr[kk] * Vd[kk * DS_STRIDE + d];
        Og[(size_t)(b * T_DEC + q) * DMODEL + h * DHEAD + d] = acc;
    }
}

// ---------------- fused residual + LayerNorm: single reduction, one barrier ----------------
__global__ void ln_res_kernel(const float* __restrict__ A, const float* __restrict__ Bv,
                              const float* __restrict__ g, const float* __restrict__ be,
                              float* __restrict__ O, uint32_t* __restrict__ Otf) {
    const int row = blockIdx.x;
    const float* a = A + (size_t)row * DMODEL;
    const float* b = Bv + (size_t)row * DMODEL;
    __shared__ float red[16];
    const int tid = threadIdx.x;
    const int lane = tid & 31, warp = tid >> 5;

    const float v0 = a[tid] + b[tid];
    const float v1 = a[tid + 256] + b[tid + 256];

    float s  = v0 + v1;
    float sq = v0 * v0 + v1 * v1;
    #pragma unroll
    for (int off = 16; off; off >>= 1) {
        s  += __shfl_xor_sync(0xffffffffu, s,  off);
        sq += __shfl_xor_sync(0xffffffffu, sq, off);
    }
    if (lane == 0) { red[warp] = s; red[warp + 8] = sq; }
    __syncthreads();
    s = red[0] + red[1] + red[2] + red[3] + red[4] + red[5] + red[6] + red[7];
    sq = red[8] + red[9] + red[10] + red[11] + red[12] + red[13] + red[14] + red[15];

    const float mean = s * (1.f / DMODEL);
    const float var  = fmaxf(sq * (1.f / DMODEL) - mean * mean, 0.f);
    const float inv  = rsqrtf(var + 1e-5f);

    const float o0 = (v0 - mean) * inv * g[tid]       + be[tid];
    const float o1 = (v1 - mean) * inv * g[tid + 256] + be[tid + 256];
    O[(size_t)row * DMODEL + tid]       = o0;
    O[(size_t)row * DMODEL + tid + 256] = o1;
    if (Otf) {
        Otf[(size_t)row * DMODEL + tid]       = f2tf32(o0);
        Otf[(size_t)row * DMODEL + tid + 256] = f2tf32(o1);
    }
}

// ---------------- host orchestration ----------------
static inline void mgemm(const uint32_t* A, const uint32_t* B, const float* bias, void* C,
                         int M, int N, int K, int relu, int tf32out,
                         int vmode = 0, uint32_t* vt = nullptr) {
    dim3 grid(N / 128, (M + 127) / 128);
    if (relu && tf32out)
        mma_gemm<1, 1><<<grid, 256, GEMM_SMEM>>>(A, B, bias, C, M, N, K, vmode, vt);
    else if (tf32out)
        mma_gemm<0, 1><<<grid, 256, GEMM_SMEM>>>(A, B, bias, C, M, N, K, vmode, vt);
    else
        mma_gemm<0, 0><<<grid, 256, GEMM_SMEM>>>(A, B, bias, C, M, N, K, vmode, vt);
}

template <typename T>
static inline void* symv(T& s) {
    void* p = nullptr;
    cudaGetSymbolAddress(&p, s);
    return p;
}

extern "C" void kernel_launch(void* const* d_in, const int* in_sizes, int n_in,
                              void* d_out, int out_size) {
    (void)in_sizes; (void)n_in; (void)out_size;

    cudaFuncSetAttribute((const void*)mma_gemm<0,0>, cudaFuncAttributeMaxDynamicSharedMemorySize, GEMM_SMEM);
    cudaFuncSetAttribute((const void*)mma_gemm<0,1>, cudaFuncAttributeMaxDynamicSharedMemorySize, GEMM_SMEM);
    cudaFuncSetAttribute((const void*)mma_gemm<1,1>, cudaFuncAttributeMaxDynamicSharedMemorySize, GEMM_SMEM);
    cudaFuncSetAttribute((const void*)flash_attn,    cudaFuncAttributeMaxDynamicSharedMemorySize, FLASH_SMEM);
    cudaFuncSetAttribute((const void*)dec_self_attn, cudaFuncAttributeMaxDynamicSharedMemorySize, DEC_SMEM);

    const float* x_in      = (const float*)d_in[0];
    const float* y_in      = (const float*)d_in[1];
    const float* enc_Wq    = (const float*)d_in[2];
    const float* enc_Wk    = (const float*)d_in[3];
    const float* enc_Wv    = (const float*)d_in[4];
    const float* enc_ff_w1 = (const float*)d_in[5];
    const float* enc_ff_b1 = (const float*)d_in[6];
    const float* enc_ff_w2 = (const float*)d_in[7];
    const float* enc_ff_b2 = (const float*)d_in[8];
    const float* enc_ln1_g = (const float*)d_in[9];
    const float* enc_ln1_b = (const float*)d_in[10];
    const float* enc_ln2_g = (const float*)d_in[11];
    const float* enc_ln2_b = (const float*)d_in[12];
    const float* dec_Wq1   = (const float*)d_in[13];
    const float* dec_Wk1   = (const float*)d_in[14];
    const float* dec_Wv1   = (const float*)d_in[15];
    const float* dec_Wq2   = (const float*)d_in[16];
    const float* dec_Wk2   = (const float*)d_in[17];
    const float* dec_Wv2   = (const float*)d_in[18];
    const float* dec_ff_w1 = (const float*)d_in[19];
    const float* dec_ff_b1 = (const float*)d_in[20];
    const float* dec_ff_w2 = (const float*)d_in[21];
    const float* dec_ff_b2 = (const float*)d_in[22];
    const float* dec_ln1_g = (const float*)d_in[23];
    const float* dec_ln1_b = (const float*)d_in[24];
    const float* dec_ln2_g = (const float*)d_in[25];
    const float* dec_ln2_b = (const float*)d_in[26];
    const float* dec_ln3_g = (const float*)d_in[27];
    const float* dec_ln3_b = (const float*)d_in[28];

    uint32_t* eqkvW = (uint32_t*)symv(w_eqkv);
    uint32_t* ew1   = (uint32_t*)symv(w_ew1);
    uint32_t* ew2   = (uint32_t*)symv(w_ew2);
    uint32_t* dqkv1 = (uint32_t*)symv(w_dqkv1);
    uint32_t* dq2   = (uint32_t*)symv(w_dq2);
    uint32_t* dkv2  = (uint32_t*)symv(w_dkv2);
    uint32_t* dw1   = (uint32_t*)symv(w_dw1);
    uint32_t* dw2   = (uint32_t*)symv(w_dw2);

    uint32_t* qkv  = (uint32_t*)symv(g_qkv);
    float*    qkvd = (float*)symv(g_qkvd);
    uint32_t* kv   = (uint32_t*)symv(g_kv);
    uint32_t* vtE  = (uint32_t*)symv(g_vtE);
    uint32_t* vtD  = (uint32_t*)symv(g_vtD);
    uint32_t* qx   = (uint32_t*)symv(g_qx);
    uint32_t* h    = (uint32_t*)symv(g_h);
    uint32_t* xtf  = (uint32_t*)symv(g_xtf);
    uint32_t* x1tf = (uint32_t*)symv(g_x1tf);
    uint32_t* ytf  = (uint32_t*)symv(g_ytf);
    uint32_t* y1tf = (uint32_t*)symv(g_y1tf);
    uint32_t* y2tf = (uint32_t*)symv(g_y2tf);
    float* att = (float*)symv(g_att);
    float* x1  = (float*)symv(g_x1);
    float* gx  = (float*)symv(g_x);
    float* y1  = (float*)symv(g_y1);
    float* y2  = (float*)symv(g_y2);
    float* gy  = (float*)symv(g_y);

    const long long WO = DMODEL * DMODEL;
    const long long FO1 = DFF * DMODEL;
    const long long LQKV = (long long)NQKV * DMODEL;

    // ---- transpose-convert ALL weights [K][N] -> [N][K] tf32 ----
    {
        TJobs tj;
        int n = 0;
        for (int i = 0; i < 2; i++) {
            tj.j[n++] = { enc_Wq + i * WO, eqkvW + i * LQKV +      0LL * DMODEL, DMODEL, DMODEL, 0.125f };
            tj.j[n++] = { enc_Wk + i * WO, eqkvW + i * LQKV +    512LL * DMODEL, DMODEL, DMODEL, 1.f };
            tj.j[n++] = { enc_Wv + i * WO, eqkvW + i * LQKV +   1024LL * DMODEL, DMODEL, DMODEL, 1.f };
            tj.j[n++] = { dec_Wq1 + i * WO, dqkv1 + i * LQKV +     0LL * DMODEL, DMODEL, DMODEL, 1.f };
            tj.j[n++] = { dec_Wk1 + i * WO, dqkv1 + i * LQKV +   512LL * DMODEL, DMODEL, DMODEL, 1.f };
            tj.j[n++] = { dec_Wv1 + i * WO, dqkv1 + i * LQKV +  1024LL * DMODEL, DMODEL, DMODEL, 1.f };
            tj.j[n++] = { dec_Wq2 + i * WO, dq2 + i * WO, DMODEL, DMODEL, 0.125f };
            tj.j[n++] = { dec_Wk2 + i * WO, dkv2 + (i * 1024LL      ) * DMODEL, DMODEL, DMODEL, 1.f };
            tj.j[n++] = { dec_Wv2 + i * WO, dkv2 + (i * 1024LL + 512) * DMODEL, DMODEL, DMODEL, 1.f };
            tj.j[n++] = { enc_ff_w1 + i * FO1, ew1 + i * FO1, DMODEL, DFF, 1.f };
            tj.j[n++] = { enc_ff_w2 + i * FO1, ew2 + i * FO1, DFF, DMODEL, 1.f };
            tj.j[n++] = { dec_ff_w1 + i * FO1, dw1 + i * FO1, DMODEL, DFF, 1.f };
            tj.j[n++] = { dec_ff_w2 + i * FO1, dw2 + i * FO1, DFF, DMODEL, 1.f };
        }
        tpack_kernel<<<dim3(64, 64, n), 256>>>(tj, n);
    }
    {
        ConvJobs jobs;
        jobs.j[0] = { (const float4*)x_in, (uint4*)xtf, (M_ENC * DMODEL) / 4 };
        jobs.j[1] = { (const float4*)y_in, (uint4*)ytf, (M_DEC * DMODEL) / 4 };
        conv_multi_kernel<<<dim3(160, 2), 256>>>(jobs, 2);
    }

    // -------- encoder --------
    const float* xc = x_in;
    for (int i = 0; i < 2; i++) {
        mgemm(xtf, eqkvW + (size_t)i * LQKV, nullptr, qkv, M_ENC, NQKV, DMODEL, 0, 1, 1, vtE);
        flash_attn<<<dim3(T_ENC / 128, BHT), 256, FLASH_SMEM>>>(
            qkv, NQKV, qkv + 512, NQKV, vtE, att, T_ENC, T_ENC);
        ln_res_kernel<<<M_ENC, 256>>>(xc, att, enc_ln1_g + i * DMODEL, enc_ln1_b + i * DMODEL, x1, x1tf);
        mgemm(x1tf, ew1 + (size_t)i * FO1, enc_ff_b1 + i * DFF, h, M_ENC, DFF, DMODEL, 1, 1);
        mgemm(h, ew2 + (size_t)i * FO1, enc_ff_b2 + i * DMODEL, att, M_ENC, DMODEL, DFF, 0, 0);
        ln_res_kernel<<<M_ENC, 256>>>(x1, att, enc_ln2_g + i * DMODEL, enc_ln2_b + i * DMODEL, gx, xtf);
        xc = gx;
    }

    // -------- decoder cross K/V for BOTH layers (one full-wave GEMM; V -> vtD d-major) --------
    mgemm(xtf, dkv2, nullptr, kv, M_ENC, NKV2, DMODEL, 0, 1, 2, vtD);

    // -------- decoder --------
    const float* yc = y_in;
    for (int i = 0; i < 2; i++) {
        // masked self-attention: exact fp32 fused path (post-softmax -1e10 fill)
        mgemm(ytf, dqkv1 + (size_t)i * LQKV, nullptr, qkvd, M_DEC, NQKV, DMODEL, 0, 0);
        dec_self_attn<<<BHT, 256, DEC_SMEM>>>(qkvd, att);
        ln_res_kernel<<<M_DEC, 256>>>(yc, att, dec_ln1_g + i * DMODEL, dec_ln1_b + i * DMODEL, y1, y1tf);

        // cross-attention (non-causal -> flash; K/V precomputed, V d-major)
        mgemm(y1tf, dq2 + i * WO, nullptr, qx, M_DEC, DMODEL, DMODEL, 0, 1);
        flash_attn<<<dim3(1, BHT), 256, FLASH_SMEM>>>(
            qx, DMODEL, kv + (size_t)i * 1024, NKV2,
            vtD + (size_t)i * BHT * DHEAD * T_ENC, att, T_DEC, T_ENC);
        ln_res_kernel<<<M_DEC, 256>>>(y1, att, dec_ln2_g + i * DMODEL, dec_ln2_b + i * DMODEL, y2, y2tf);

        // feed-forward
        mgemm(y2tf, dw1 + (size_t)i * FO1, dec_ff_b1 + i * DFF, h, M_DEC, DFF, DMODEL, 1, 1);
        mgemm(h, dw2 + (size_t)i * FO1, dec_ff_b2 + i * DMODEL, att, M_DEC, DMODEL, DFF, 0, 0);
        float* outp = (i == 1) ? (float*)d_out : gy;
        ln_res_kernel<<<M_DEC, 256>>>(y2, att, dec_ln3_g + i * DMODEL, dec_ln3_b + i * DMODEL,
                                      outp, (i == 1) ? nullptr : ytf);
        yc = gy;
    }
}

// round 16
// speedup vs baseline: 1.1248x; 1.1248x over previous
#include <cuda_runtime.h>
#include <cstdint>
#include <cstddef>

// ---------------- problem constants ----------------
#define BATCH   8
#define T_ENC   1024
#define T_DEC   100
#define DMODEL  512
#define NHEAD   8
#define DHEAD   64
#define DFF     2048
#define M_ENC   (BATCH * T_ENC)   // 8192
#define M_DEC   (BATCH * T_DEC)   // 800
#define BHT     (BATCH * NHEAD)   // 64
#define NQKV    1536
#define NKV2    2048              // both decoder layers' K|V fused along N

// ---------------- fused tf32 weights, TRANSPOSED [N][K] ----------------
__device__ uint32_t w_eqkv[2 * NQKV * DMODEL];
__device__ uint32_t w_ew1 [2 * DFF * DMODEL];
__device__ uint32_t w_ew2 [2 * DMODEL * DFF];
__device__ uint32_t w_dqkv1[2 * NQKV * DMODEL];
__device__ uint32_t w_dq2 [2 * DMODEL * DMODEL];
__device__ uint32_t w_dkv2[NKV2 * DMODEL];
__device__ uint32_t w_dw1 [2 * DFF * DMODEL];
__device__ uint32_t w_dw2 [2 * DMODEL * DFF];

// ---------------- activations / scratch ----------------
__device__ uint32_t g_qkv [M_ENC * NQKV];        // enc Q|K (tf32); V region unused
__device__ float    g_qkvd[M_DEC * NQKV];        // dec self QKV (fp32 exact)
__device__ uint32_t g_kv  [M_ENC * NKV2];        // dec cross K both layers; V regions unused
__device__ uint32_t g_vtE [BHT * DHEAD * T_ENC]; // enc V, d-major [bh][64][1024]
__device__ uint32_t g_vtD [2 * BHT * DHEAD * T_ENC]; // dec cross V, per layer
__device__ uint32_t g_qx  [M_DEC * DMODEL];
__device__ uint32_t g_h   [M_ENC * DFF];
__device__ uint32_t g_xtf [M_ENC * DMODEL];
__device__ uint32_t g_x1tf[M_ENC * DMODEL];
__device__ uint32_t g_ytf [M_DEC * DMODEL];
__device__ uint32_t g_y1tf[M_DEC * DMODEL];
__device__ uint32_t g_y2tf[M_DEC * DMODEL];
__device__ float g_att [M_ENC * DMODEL];
__device__ float g_x1  [M_ENC * DMODEL];
__device__ float g_x   [M_ENC * DMODEL];
__device__ float g_y1  [M_DEC * DMODEL];
__device__ float g_y2  [M_DEC * DMODEL];
__device__ float g_y   [M_DEC * DMODEL];

__device__ __forceinline__ uint32_t f2tf32(float x) {
    uint32_t t;
    asm("cvt.rna.tf32.f32 %0, %1;" : "=r"(t) : "f"(x));
    return t;
}

__device__ __forceinline__ void mma8(float* c, const uint32_t* a, uint32_t b0, uint32_t b1) {
    asm volatile(
        "mma.sync.aligned.m16n8k8.row.col.f32.tf32.tf32.f32 "
        "{%0,%1,%2,%3}, {%4,%5,%6,%7}, {%8,%9}, {%0,%1,%2,%3};"
        : "+f"(c[0]), "+f"(c[1]), "+f"(c[2]), "+f"(c[3])
        : "r"(a[0]), "r"(a[1]), "r"(a[2]), "r"(a[3]), "r"(b0), "r"(b1));
}

__device__ __forceinline__ void ldsm4(uint32_t& r0, uint32_t& r1, uint32_t& r2, uint32_t& r3,
                                      uint32_t addr) {
    asm volatile("ldmatrix.sync.aligned.m8n8.x4.shared.b16 {%0,%1,%2,%3}, [%4];"
                 : "=r"(r0), "=r"(r1), "=r"(r2), "=r"(r3) : "r"(addr));
}

__device__ __forceinline__ void cpasync16(uint32_t smem_dst, const void* gsrc, int bytes) {
    asm volatile("cp.async.ca.shared.global [%0], [%1], 16, %2;"
                 :: "r"(smem_dst), "l"(gsrc), "r"(bytes));
}

__device__ __forceinline__ uint4 cvt4(float4 v) {
    return make_uint4(f2tf32(v.x), f2tf32(v.y), f2tf32(v.z), f2tf32(v.w));
}

// ---------------- transpose-convert packing: src [K][N] fp32 -> dst [N][K] tf32 ----------------
struct TJob { const float* src; uint32_t* dst; int K; int N; float scale; };
struct TJobs { TJob j[26]; };

__global__ void tpack_kernel(TJobs jobs, int njobs) {
    const int job = blockIdx.z;
    if (job >= njobs) return;
    const TJob jb = jobs.j[job];
    const int nt = blockIdx.x << 5, kt = blockIdx.y << 5;
    if (nt >= jb.N || kt >= jb.K) return;
    __shared__ float tile[32][33];
    const int tx = threadIdx.x & 31, ty = threadIdx.x >> 5;
    #pragma unroll
    for (int i = 0; i < 4; i++) {
        int k = kt + ty + i * 8;
        tile[ty + i * 8][tx] = jb.src[(size_t)k * jb.N + nt + tx];
    }
    __syncthreads();
    #pragma unroll
    for (int i = 0; i < 4; i++) {
        int n = nt + ty + i * 8;
        jb.dst[(size_t)n * jb.K + kt + tx] = f2tf32(tile[tx][ty + i * 8] * jb.scale);
    }
}

// ---------------- plain conversion (x / y inputs) ----------------
struct ConvJob { const float4* src; uint4* dst; int n4; };
struct ConvJobs { ConvJob j[2]; };

__global__ void conv_multi_kernel(ConvJobs jobs, int njobs) {
    int seg = blockIdx.y;
    if (seg >= njobs) return;
    ConvJob jb = jobs.j[seg];
    for (int i = blockIdx.x * blockDim.x + threadIdx.x; i < jb.n4; i += gridDim.x * blockDim.x) {
        jb.dst[i] = cvt4(jb.src[i]);
    }
}

// ================= 2-stage cp.async tf32 GEMM (ldmatrix A+B; V-transpose epilogue) =================
// R14 proven configuration: 72KB smem, 2 CTAs/SM.
#define GA_STRIDE 36
#define GA_STAGE  (128 * GA_STRIDE)
#define GB_STAGE  (128 * GA_STRIDE)
#define GEMM_SMEM ((2 * GA_STAGE + 2 * GB_STAGE) * 4)

template<int RELU, int TF32OUT>
__global__ __launch_bounds__(256)
void mma_gemm(const uint32_t* __restrict__ A, const uint32_t* __restrict__ B,
              const float* __restrict__ bias, void* __restrict__ Cv,
              int M, int N, int K, int vmode, uint32_t* __restrict__ vt)
{
    extern __shared__ uint32_t gsm[];
    uint32_t* Asf = gsm;
    uint32_t* Bsf = gsm + 2 * GA_STAGE;

    const int tid  = threadIdx.x;
    const int wid  = tid >> 5, lane = tid & 31;
    const int wm   = wid & 1, wn = wid >> 1;
    const int g    = lane >> 2, tig = lane & 3;
    const int m0   = blockIdx.y * 128, n0 = blockIdx.x * 128;

    const int lt = lane >> 3, lr = lane & 7;
    const int a_row = lr + ((lt & 1) << 3);
    const int a_col = (lt >> 1) << 2;
    const int b_row = lr + ((lt >> 1) << 3);
    const int b_col = (lt & 1) << 2;

    const uint32_t aBase = (uint32_t)__cvta_generic_to_shared(Asf);
    const uint32_t bBase = (uint32_t)__cvta_generic_to_shared(Bsf);

    float acc[4][4][4];
    #pragma unroll
    for (int i = 0; i < 4; i++)
        #pragma unroll
        for (int j = 0; j < 4; j++)
            #pragma unroll
            for (int c = 0; c < 4; c++) acc[i][j][c] = 0.f;

    auto issue = [&](int s, int k0) {
        #pragma unroll
        for (int i = 0; i < 4; i++) {
            int idx = tid + (i << 8);
            int r = idx >> 3, kk4 = (idx & 7) << 2;
            int m = m0 + r;
            const uint32_t* src = A + (size_t)(m < M ? m : 0) * K + k0 + kk4;
            cpasync16(aBase + (s * GA_STAGE + r * GA_STRIDE + kk4) * 4, src, (m < M) ? 16 : 0);
        }
        #pragma unroll
        for (int i = 0; i < 4; i++) {
            int idx = tid + (i << 8);
            int r = idx >> 3, kk4 = (idx & 7) << 2;
            const uint32_t* src = B + (size_t)(n0 + r) * K + k0 + kk4;
            cpasync16(bBase + (s * GB_STAGE + r * GA_STRIDE + kk4) * 4, src, 16);
        }
        asm volatile("cp.async.commit_group;");
    };

    const int nk = K >> 5;
    issue(0, 0);

    for (int kt = 0; kt < nk; kt++) {
        const int s = kt & 1;
        if (kt + 1 < nk) {
            issue(s ^ 1, (kt + 1) << 5);
            asm volatile("cp.async.wait_group 1;");
        } else {
            asm volatile("cp.async.wait_group 0;");
        }
        __syncthreads();

        const uint32_t aLane = aBase +
            (s * GA_STAGE + (wm * 64 + a_row) * GA_STRIDE + a_col) * 4;
        const uint32_t bLane = bBase +
            (s * GB_STAGE + (wn * 32 + b_row) * GA_STRIDE + b_col) * 4;
        #pragma unroll
        for (int ks = 0; ks < 32; ks += 8) {
            uint32_t af[4][4];
            #pragma unroll
            for (int mi = 0; mi < 4; mi++)
                ldsm4(af[mi][0], af[mi][1], af[mi][2], af[mi][3],
                      aLane + (mi * 16 * GA_STRIDE + ks) * 4);
            uint32_t bf[4][2];
            ldsm4(bf[0][0], bf[0][1], bf[1][0], bf[1][1], bLane + ks * 4);
            ldsm4(bf[2][0], bf[2][1], bf[3][0], bf[3][1],
                  bLane + (16 * GA_STRIDE + ks) * 4);
            #pragma unroll
            for (int mi = 0; mi < 4; mi++)
                #pragma unroll
                for (int ni = 0; ni < 4; ni++)
                    mma8(acc[mi][ni], af[mi], bf[ni][0], bf[ni][1]);
        }
        __syncthreads();
    }

    // ---- epilogue ----
    bool vtile = false;
    int vrow0 = 0;
    if (TF32OUT && vmode) {
        if (vmode == 1 && n0 >= 1024) {
            vtile = true;
            vrow0 = (m0 >> 10) * 512 + (n0 - 1024);
        } else if (vmode == 2 && (n0 & 512)) {
            vtile = true;
            vrow0 = (n0 >> 10) * 4096 + (m0 >> 10) * 512 + ((n0 & 1023) - 512);
        }
    }

    if (!vtile) {
        #pragma unroll
        for (int mi = 0; mi < 4; mi++) {
            int mb = m0 + wm * 64 + mi * 16;
            #pragma unroll
            for (int ni = 0; ni < 4; ni++) {
                int nb = n0 + wn * 32 + ni * 8 + 2 * tig;
                #pragma unroll
                for (int half = 0; half < 2; half++) {
                    int m = mb + g + half * 8;
                    if (m < M) {
                        float v0 = acc[mi][ni][half * 2    ];
                        float v1 = acc[mi][ni][half * 2 + 1];
                        if (bias) { v0 += bias[nb]; v1 += bias[nb + 1]; }
                        if (RELU) { v0 = fmaxf(v0, 0.f); v1 = fmaxf(v1, 0.f); }
                        if (TF32OUT) {
                            *(uint2*)((uint32_t*)Cv + (size_t)m * N + nb) =
                                make_uint2(f2tf32(v0), f2tf32(v1));
                        } else {
                            *(float2*)((float*)Cv + (size_t)m * N + nb) = make_float2(v0, v1);
                        }
                    }
                }
            }
        }
    } else {
        uint32_t* st = gsm;   // 128 x 132 (<= GEMM smem)
        #pragma unroll
        for (int mi = 0; mi < 4; mi++) {
            int mloc = wm * 64 + mi * 16 + g;
            #pragma unroll
            for (int ni = 0; ni < 4; ni++) {
                int nloc = wn * 32 + ni * 8 + 2 * tig;
                st[(nloc    ) * 132 + mloc    ] = f2tf32(acc[mi][ni][0]);
                st[(nloc + 1) * 132 + mloc    ] = f2tf32(acc[mi][ni][1]);
                st[(nloc    ) * 132 + mloc + 8] = f2tf32(acc[mi][ni][2]);
                st[(nloc + 1) * 132 + mloc + 8] = f2tf32(acc[mi][ni][3]);
            }
        }
        __syncthreads();
        const int tok0 = m0 & 1023;
        #pragma unroll
        for (int it = 0; it < 16; it++) {
            int idx = tid + (it << 8);
            int r = idx >> 5, ch = (idx & 31) << 2;
            uint4 v = *(uint4*)&st[r * 132 + ch];
            *(uint4*)(vt + (size_t)(vrow0 + r) * 1024 + tok0 + ch) = v;
        }
    }
}

// ================= fused flash attention (non-causal, exact) — R12 proven =================
// 2-stage KV pipeline; Q hoisted to registers; P in registers via quad shuffles;
// V d-major. smem = KV double buffers only (70KB).
#define FQ_STRIDE 68
#define FKV_STAGE (64 * FQ_STRIDE)
#define FLASH_SMEM ((4 * FKV_STAGE) * 4)

__global__ __launch_bounds__(256, 2)
void flash_attn(const uint32_t* __restrict__ Qg, int ldq,
                const uint32_t* __restrict__ Kg, int ldkv,
                const uint32_t* __restrict__ Vt,
                float* __restrict__ Og, int Tq, int Tk)
{
    extern __shared__ uint32_t fsm[];
    uint32_t* Kraw = fsm;                    // 2 x [64][68]
    uint32_t* Vraw = fsm + 2 * FKV_STAGE;    // 2 x [64][68]

    const int bh = blockIdx.y;
    const int b = bh >> 3, h = bh & 7;
    const int q0 = blockIdx.x * 128;
    const int tid = threadIdx.x;
    const int wid = tid >> 5, lane = tid & 31;
    const int g = lane >> 2, tig = lane & 3;
    const int mr = wid * 16;

    const int lt = lane >> 3, lr = lane & 7;
    const int a_row = lr + ((lt & 1) << 3);
    const int a_col = (lt >> 1) << 2;
    const int k_row = lr + ((lt >> 1) << 3);
    const int k_col = (lt & 1) << 2;

    const uint32_t* qp = Qg + (size_t)b * Tq * ldq + h * DHEAD;
    const uint32_t* kp = Kg + (size_t)b * Tk * ldkv + h * DHEAD;
    const uint32_t* vp = Vt + (size_t)bh * 64 * Tk;

    const uint32_t kBase = (uint32_t)__cvta_generic_to_shared(Kraw);
    const uint32_t vBase = (uint32_t)__cvta_generic_to_shared(Vraw);

    // ---- stage Q (128 x 64) through the 128-row K+V buffer space, hoist to regs ----
    #pragma unroll
    for (int i = 0; i < 8; i++) {
        int idx = tid + (i << 8);
        int r = idx >> 4, d4 = (idx & 15) << 2;
        int q = q0 + r;
        cpasync16(kBase + (r * FQ_STRIDE + d4) * 4,
                  qp + (size_t)(q < Tq ? q : 0) * ldq + d4, 16);
    }
    asm volatile("cp.async.commit_group;");
    asm volatile("cp.async.wait_group 0;");
    __syncthreads();
    uint32_t qf[8][4];
    {
        const uint32_t qLane = kBase + ((mr + a_row) * FQ_STRIDE + a_col) * 4;
        #pragma unroll
        for (int j = 0; j < 8; j++)
            ldsm4(qf[j][0], qf[j][1], qf[j][2], qf[j][3], qLane + (j << 5));
    }
    __syncthreads();   // all warps done reading Q before KV overwrites the buffer

    auto issueKV = [&](int s, int kt) {
        #pragma unroll
        for (int i = 0; i < 4; i++) {
            int idx = tid + (i << 8);
            int r = idx >> 4, d4 = (idx & 15) << 2;
            cpasync16(kBase + (s * FKV_STAGE + r * FQ_STRIDE + d4) * 4,
                      kp + (size_t)(kt + r) * ldkv + d4, 16);
            cpasync16(vBase + (s * FKV_STAGE + r * FQ_STRIDE + d4) * 4,
                      vp + (size_t)r * Tk + kt + d4, 16);
        }
        asm volatile("cp.async.commit_group;");
    };

    issueKV(0, 0);

    float o[8][4];
    #pragma unroll
    for (int ni = 0; ni < 8; ni++)
        #pragma unroll
        for (int c = 0; c < 4; c++) o[ni][c] = 0.f;
    float m0 = -1e30f, m1 = -1e30f, l0 = 0.f, l1 = 0.f;

    const int srcA = (lane & ~3) | (tig >> 1);
    const int srcB = srcA + 2;
    const bool odd = tig & 1;

    const int nt = Tk >> 6;
    for (int kt = 0; kt < nt; kt++) {
        const int s = kt & 1;
        if (kt + 1 < nt) {
            issueKV(s ^ 1, (kt + 1) << 6);
            asm volatile("cp.async.wait_group 1;");
        } else {
            asm volatile("cp.async.wait_group 0;");
        }
        __syncthreads();

        const uint32_t kLane = kBase + (s * FKV_STAGE + k_row * FQ_STRIDE + k_col) * 4;
        const uint32_t vLane = vBase + (s * FKV_STAGE + k_row * FQ_STRIDE + k_col) * 4;

        // ---- S = Q @ K^T (Q from registers) ----
        float sfr[8][4];
        #pragma unroll
        for (int ni = 0; ni < 8; ni++)
            #pragma unroll
            for (int c = 0; c < 4; c++) sfr[ni][c] = 0.f;
        #pragma unroll
        for (int j = 0; j < 8; j++) {
            const int ks = j * 8;
            #pragma unroll
            for (int np = 0; np < 8; np += 2) {
                uint32_t b00, b01, b10, b11;
                ldsm4(b00, b01, b10, b11, kLane + (np * 8 * FQ_STRIDE + ks) * 4);
                mma8(sfr[np    ], qf[j], b00, b01);
                mma8(sfr[np + 1], qf[j], b10, b11);
            }
        }

        // ---- online softmax; tf32 P bits stored in-place in sfr ----
        float tmax0 = -1e30f, tmax1 = -1e30f;
        #pragma unroll
        for (int ni = 0; ni < 8; ni++) {
            tmax0 = fmaxf(tmax0, fmaxf(sfr[ni][0], sfr[ni][1]));
            tmax1 = fmaxf(tmax1, fmaxf(sfr[ni][2], sfr[ni][3]));
        }
        #pragma unroll
        for (int off = 1; off <= 2; off <<= 1) {
            tmax0 = fmaxf(tmax0, __shfl_xor_sync(0xffffffffu, tmax0, off));
            tmax1 = fmaxf(tmax1, __shfl_xor_sync(0xffffffffu, tmax1, off));
        }
        const float mn0 = fmaxf(m0, tmax0), mn1 = fmaxf(m1, tmax1);
        const float a0 = __expf(m0 - mn0), a1 = __expf(m1 - mn1);
        float rs0 = 0.f, rs1 = 0.f;
        #pragma unroll
        for (int ni = 0; ni < 8; ni++) {
            float p0 = __expf(sfr[ni][0] - mn0);
            float p1 = __expf(sfr[ni][1] - mn0);
            float p2 = __expf(sfr[ni][2] - mn1);
            float p3 = __expf(sfr[ni][3] - mn1);
            rs0 += p0 + p1; rs1 += p2 + p3;
            sfr[ni][0] = __uint_as_float(f2tf32(p0));
            sfr[ni][1] = __uint_as_float(f2tf32(p1));
            sfr[ni][2] = __uint_as_float(f2tf32(p2));
            sfr[ni][3] = __uint_as_float(f2tf32(p3));
        }
        #pragma unroll
        for (int off = 1; off <= 2; off <<= 1) {
            rs0 += __shfl_xor_sync(0xffffffffu, rs0, off);
            rs1 += __shfl_xor_sync(0xffffffffu, rs1, off);
        }
        l0 = l0 * a0 + rs0; l1 = l1 * a1 + rs1;
        m0 = mn0; m1 = mn1;
        #pragma unroll
        for (int ni = 0; ni < 8; ni++) {
            o[ni][0] *= a0; o[ni][1] *= a0;
            o[ni][2] *= a1; o[ni][3] *= a1;
        }

        // ---- O += P @ V : P c-frag -> a-frag via quad shuffles; V via ldmatrix ----
        #pragma unroll
        for (int j = 0; j < 8; j++) {
            uint32_t p0 = __float_as_uint(sfr[j][0]);
            uint32_t p1 = __float_as_uint(sfr[j][1]);
            uint32_t p2 = __float_as_uint(sfr[j][2]);
            uint32_t p3 = __float_as_uint(sfr[j][3]);
            uint32_t r0a = __shfl_sync(0xffffffffu, p0, srcA);
            uint32_t r1a = __shfl_sync(0xffffffffu, p1, srcA);
            uint32_t r2a = __shfl_sync(0xffffffffu, p2, srcA);
            uint32_t r3a = __shfl_sync(0xffffffffu, p3, srcA);
            uint32_t r0b = __shfl_sync(0xffffffffu, p0, srcB);
            uint32_t r1b = __shfl_sync(0xffffffffu, p1, srcB);
            uint32_t r2b = __shfl_sync(0xffffffffu, p2, srcB);
            uint32_t r3b = __shfl_sync(0xffffffffu, p3, srcB);
            uint32_t af[4];
            af[0] = odd ? r1a : r0a;
            af[1] = odd ? r3a : r2a;
            af[2] = odd ? r1b : r0b;
            af[3] = odd ? r3b : r2b;
            const int ks = j * 8;
            #pragma unroll
            for (int np = 0; np < 8; np += 2) {
                uint32_t b00, b01, b10, b11;
                ldsm4(b00, b01, b10, b11, vLane + (np * 8 * FQ_STRIDE + ks) * 4);
                mma8(o[np    ], af, b00, b01);
                mma8(o[np + 1], af, b10, b11);
            }
        }
        __syncthreads();
    }

    const float i0 = 1.f / l0, i1 = 1.f / l1;
    #pragma unroll
    for (int ni = 0; ni < 8; ni++) {
        int col = h * DHEAD + ni * 8 + 2 * tig;
        int r0 = q0 + mr + g, r1 = r0 + 8;
        if (r0 < Tq)
            *(float2*)(Og + (size_t)(b * Tq + r0) * DMODEL + col) =
                make_float2(o[ni][0] * i0, o[ni][1] * i0);
        if (r1 < Tq)
            *(float2*)(Og + (size_t)(b * Tq + r1) * DMODEL + col) =
                make_float2(o[ni][2] * i1, o[ni][3] * i1);
    }
}

// ================= fused decoder self-attention (exact fp32) =================
#define DS_STRIDE 68
#define DS_SSTRIDE 104
#define DEC_SMEM ((3 * T_DEC * DS_STRIDE + T_DEC * DS_SSTRIDE) * 4)

__global__ __launch_bounds__(256)
void dec_self_attn(const float* __restrict__ QKV, float* __restrict__ Og)
{
    extern __shared__ float dsm[];
    float* Qd = dsm;
    float* Kd = Qd + T_DEC * DS_STRIDE;
    float* Vd = Kd + T_DEC * DS_STRIDE;
    float* Sd = Vd + T_DEC * DS_STRIDE;

    const int bh = blockIdx.x;
    const int b = bh >> 3, h = bh & 7;
    const int tid = threadIdx.x;
    const int wid = tid >> 5, lane = tid & 31;

    const float* qp = QKV + (size_t)b * T_DEC * NQKV + h * DHEAD;
    const float* kp = qp + 512;
    const float* vp = qp + 1024;

    for (int idx = tid; idx < T_DEC * 16; idx += 256) {
        int r = idx >> 4, d4 = (idx & 15) << 2;
        *(float4*)&Qd[r * DS_STRIDE + d4] = *(const float4*)(qp + (size_t)r * NQKV + d4);
        *(float4*)&Kd[r * DS_STRIDE + d4] = *(const float4*)(kp + (size_t)r * NQKV + d4);
        *(float4*)&Vd[r * DS_STRIDE + d4] = *(const float4*)(vp + (size_t)r * NQKV + d4);
    }
    __syncthreads();

    for (int e = tid; e < T_DEC * T_DEC; e += 256) {
        int q = e / T_DEC, kk = e - q * T_DEC;
        const float* qr = &Qd[q * DS_STRIDE];
        const float* kr = &Kd[kk * DS_STRIDE];
        float acc = 0.f;
        #pragma unroll
        for (int d = 0; d < 64; d++) acc += qr[d] * kr[d];
        Sd[q * DS_SSTRIDE + kk] = acc * 0.125f;
    }
    __syncthreads();

    for (int q = wid; q < T_DEC; q += 8) {
        float* row = &Sd[q * DS_SSTRIDE];
        float r0 = (lane      < T_DEC) ? row[lane]      : -1e30f;
        float r1 = (lane + 32 < T_DEC) ? row[lane + 32] : -1e30f;
        float r2 = (lane + 64 < T_DEC) ? row[lane + 64] : -1e30f;
        float r3 = (lane + 96 < T_DEC) ? row[lane + 96] : -1e30f;
        float m = fmaxf(fmaxf(r0, r1), fmaxf(r2, r3));
        #pragma unroll
        for (int off = 16; off; off >>= 1) m = fmaxf(m, __shfl_xor_sync(0xffffffffu, m, off));
        float e0 = expf(r0 - m), e1 = expf(r1 - m), e2 = expf(r2 - m), e3 = expf(r3 - m);
        if (lane      >= T_DEC) e0 = 0.f;
        if (lane + 32 >= T_DEC) e1 = 0.f;
        if (lane + 64 >= T_DEC) e2 = 0.f;
        if (lane + 96 >= T_DEC) e3 = 0.f;
        float s = e0 + e1 + e2 + e3;
        #pragma unroll
        for (int off = 16; off; off >>= 1) s += __shfl_xor_sync(0xffffffffu, s, off);
        const float inv = 1.f / s;
        if (lane      < T_DEC) row[lane]      = (lane      > q) ? -1e10f : e0 * inv;
        if (lane + 32 < T_DEC) row[lane + 32] = (lane + 32 > q) ? -1e10f : e1 * inv;
        if (lane + 64 < T_DEC) row[lane + 64] = (lane + 64 > q) ? -1e10f : e2 * inv;
        if (lane + 96 < T_DEC) row[lane + 96] = (lane + 96 > q) ? -1e10f : e3 * inv;
    }
    __syncthreads();

    for (int e = tid; e < T_DEC * 64; e += 256) {
        int q = e >> 6, d = e & 63;
        const float* pr = &Sd[q * DS_SSTRIDE];
        float acc = 0.f;
        #pragma unroll 4
        for (int kk = 0; kk < T_DEC; kk++) acc += pr[kk] * Vd[kk * DS_STRIDE + d];
        Og[(size_t)(b * T_DEC + q) * DMODEL + h * DHEAD + d] = acc;
    }
}

// ---------------- fused residual + LayerNorm: 1 barrier, vectorized (float2) ----------------
__global__ void ln_res_kernel(const float* __restrict__ A, const float* __restrict__ Bv,
                              const float* __restrict__ g, const float* __restrict__ be,
                              float* __restrict__ O, uint32_t* __restrict__ Otf) {
    const int row = blockIdx.x;
    const float* a = A + (size_t)row * DMODEL;
    const float* b = Bv + (size_t)row * DMODEL;
    __shared__ float red[16];
    const int tid = threadIdx.x;
    const int lane = tid & 31, warp = tid >> 5;
    const int e0i = tid << 1;   // this thread owns elements (2*tid, 2*tid+1)

    const float2 av = *(const float2*)(a + e0i);
    const float2 bv = *(const float2*)(b + e0i);
    const float v0 = av.x + bv.x;
    const float v1 = av.y + bv.y;

    float s  = v0 + v1;
    float sq = v0 * v0 + v1 * v1;
    #pragma unroll
    for (int off = 16; off; off >>= 1) {
        s  += __shfl_xor_sync(0xffffffffu, s,  off);
        sq += __shfl_xor_sync(0xffffffffu, sq, off);
    }
    if (lane == 0) { red[warp] = s; red[warp + 8] = sq; }
    __syncthreads();
    s = red[0] + red[1] + red[2] + red[3] + red[4] + red[5] + red[6] + red[7];
    sq = red[8] + red[9] + red[10] + red[11] + red[12] + red[13] + red[14] + red[15];

    const float mean = s * (1.f / DMODEL);
    const float var  = fmaxf(sq * (1.f / DMODEL) - mean * mean, 0.f);
    const float inv  = rsqrtf(var + 1e-5f);

    const float2 gv = *(const float2*)(g + e0i);
    const float2 bev = *(const float2*)(be + e0i);
    const float o0 = (v0 - mean) * inv * gv.x + bev.x;
    const float o1 = (v1 - mean) * inv * gv.y + bev.y;
    *(float2*)(O + (size_t)row * DMODEL + e0i) = make_float2(o0, o1);
    if (Otf) {
        *(uint2*)(Otf + (size_t)row * DMODEL + e0i) = make_uint2(f2tf32(o0), f2tf32(o1));
    }
}

// ---------------- host orchestration ----------------
static inline void mgemm(const uint32_t* A, const uint32_t* B, const float* bias, void* C,
                         int M, int N, int K, int relu, int tf32out,
                         int vmode = 0, uint32_t* vt = nullptr) {
    dim3 grid(N / 128, (M + 127) / 128);
    if (relu && tf32out)
        mma_gemm<1, 1><<<grid, 256, GEMM_SMEM>>>(A, B, bias, C, M, N, K, vmode, vt);
    else if (tf32out)
        mma_gemm<0, 1><<<grid, 256, GEMM_SMEM>>>(A, B, bias, C, M, N, K, vmode, vt);
    else
        mma_gemm<0, 0><<<grid, 256, GEMM_SMEM>>>(A, B, bias, C, M, N, K, vmode, vt);
}

template <typename T>
static inline void* symv(T& s) {
    void* p = nullptr;
    cudaGetSymbolAddress(&p, s);
    return p;
}

extern "C" void kernel_launch(void* const* d_in, const int* in_sizes, int n_in,
                              void* d_out, int out_size) {
    (void)in_sizes; (void)n_in; (void)out_size;

    cudaFuncSetAttribute((const void*)mma_gemm<0,0>, cudaFuncAttributeMaxDynamicSharedMemorySize, GEMM_SMEM);
    cudaFuncSetAttribute((const void*)mma_gemm<0,1>, cudaFuncAttributeMaxDynamicSharedMemorySize, GEMM_SMEM);
    cudaFuncSetAttribute((const void*)mma_gemm<1,1>, cudaFuncAttributeMaxDynamicSharedMemorySize, GEMM_SMEM);
    cudaFuncSetAttribute((const void*)flash_attn,    cudaFuncAttributeMaxDynamicSharedMemorySize, FLASH_SMEM);
    cudaFuncSetAttribute((const void*)dec_self_attn, cudaFuncAttributeMaxDynamicSharedMemorySize, DEC_SMEM);

    const float* x_in      = (const float*)d_in[0];
    const float* y_in      = (const float*)d_in[1];
    const float* enc_Wq    = (const float*)d_in[2];
    const float* enc_Wk    = (const float*)d_in[3];
    const float* enc_Wv    = (const float*)d_in[4];
    const float* enc_ff_w1 = (const float*)d_in[5];
    const float* enc_ff_b1 = (const float*)d_in[6];
    const float* enc_ff_w2 = (const float*)d_in[7];
    const float* enc_ff_b2 = (const float*)d_in[8];
    const float* enc_ln1_g = (const float*)d_in[9];
    const float* enc_ln1_b = (const float*)d_in[10];
    const float* enc_ln2_g = (const float*)d_in[11];
    const float* enc_ln2_b = (const float*)d_in[12];
    const float* dec_Wq1   = (const float*)d_in[13];
    const float* dec_Wk1   = (const float*)d_in[14];
    const float* dec_Wv1   = (const float*)d_in[15];
    const float* dec_Wq2   = (const float*)d_in[16];
    const float* dec_Wk2   = (const float*)d_in[17];
    const float* dec_Wv2   = (const float*)d_in[18];
    const float* dec_ff_w1 = (const float*)d_in[19];
    const float* dec_ff_b1 = (const float*)d_in[20];
    const float* dec_ff_w2 = (const float*)d_in[21];
    const float* dec_ff_b2 = (const float*)d_in[22];
    const float* dec_ln1_g = (const float*)d_in[23];
    const float* dec_ln1_b = (const float*)d_in[24];
    const float* dec_ln2_g = (const float*)d_in[25];
    const float* dec_ln2_b = (const float*)d_in[26];
    const float* dec_ln3_g = (const float*)d_in[27];
    const float* dec_ln3_b = (const float*)d_in[28];

    uint32_t* eqkvW = (uint32_t*)symv(w_eqkv);
    uint32_t* ew1   = (uint32_t*)symv(w_ew1);
    uint32_t* ew2   = (uint32_t*)symv(w_ew2);
    uint32_t* dqkv1 = (uint32_t*)symv(w_dqkv1);
    uint32_t* dq2   = (uint32_t*)symv(w_dq2);
    uint32_t* dkv2  = (uint32_t*)symv(w_dkv2);
    uint32_t* dw1   = (uint32_t*)symv(w_dw1);
    uint32_t* dw2   = (uint32_t*)symv(w_dw2);

    uint32_t* qkv  = (uint32_t*)symv(g_qkv);
    float*    qkvd = (float*)symv(g_qkvd);
    uint32_t* kv   = (uint32_t*)symv(g_kv);
    uint32_t* vtE  = (uint32_t*)symv(g_vtE);
    uint32_t* vtD  = (uint32_t*)symv(g_vtD);
    uint32_t* qx   = (uint32_t*)symv(g_qx);
    uint32_t* h    = (uint32_t*)symv(g_h);
    uint32_t* xtf  = (uint32_t*)symv(g_xtf);
    uint32_t* x1tf = (uint32_t*)symv(g_x1tf);
    uint32_t* ytf  = (uint32_t*)symv(g_ytf);
    uint32_t* y1tf = (uint32_t*)symv(g_y1tf);
    uint32_t* y2tf = (uint32_t*)symv(g_y2tf);
    float* att = (float*)symv(g_att);
    float* x1  = (float*)symv(g_x1);
    float* gx  = (float*)symv(g_x);
    float* y1  = (float*)symv(g_y1);
    float* y2  = (float*)symv(g_y2);
    float* gy  = (float*)symv(g_y);

    const long long WO = DMODEL * DMODEL;
    const long long FO1 = DFF * DMODEL;
    const long long LQKV = (long long)NQKV * DMODEL;

    // ---- transpose-convert ALL weights [K][N] -> [N][K] tf32 ----
    {
        TJobs tj;
        int n = 0;
        for (int i = 0; i < 2; i++) {
            tj.j[n++] = { enc_Wq + i * WO, eqkvW + i * LQKV +      0LL * DMODEL, DMODEL, DMODEL, 0.125f };
            tj.j[n++] = { enc_Wk + i * WO, eqkvW + i * LQKV +    512LL * DMODEL, DMODEL, DMODEL, 1.f };
            tj.j[n++] = { enc_Wv + i * WO, eqkvW + i * LQKV +   1024LL * DMODEL, DMODEL, DMODEL, 1.f };
            tj.j[n++] = { dec_Wq1 + i * WO, dqkv1 + i * LQKV +     0LL * DMODEL, DMODEL, DMODEL, 1.f };
            tj.j[n++] = { dec_Wk1 + i * WO, dqkv1 + i * LQKV +   512LL * DMODEL, DMODEL, DMODEL, 1.f };
            tj.j[n++] = { dec_Wv1 + i * WO, dqkv1 + i * LQKV +  1024LL * DMODEL, DMODEL, DMODEL, 1.f };
            tj.j[n++] = { dec_Wq2 + i * WO, dq2 + i * WO, DMODEL, DMODEL, 0.125f };
            tj.j[n++] = { dec_Wk2 + i * WO, dkv2 + (i * 1024LL      ) * DMODEL, DMODEL, DMODEL, 1.f };
            tj.j[n++] = { dec_Wv2 + i * WO, dkv2 + (i * 1024LL + 512) * DMODEL, DMODEL, DMODEL, 1.f };
            tj.j[n++] = { enc_ff_w1 + i * FO1, ew1 + i * FO1, DMODEL, DFF, 1.f };
            tj.j[n++] = { enc_ff_w2 + i * FO1, ew2 + i * FO1, DFF, DMODEL, 1.f };
            tj.j[n++] = { dec_ff_w1 + i * FO1, dw1 + i * FO1, DMODEL, DFF, 1.f };
            tj.j[n++] = { dec_ff_w2 + i * FO1, dw2 + i * FO1, DFF, DMODEL, 1.f };
        }
        tpack_kernel<<<dim3(64, 64, n), 256>>>(tj, n);
    }
    {
        ConvJobs jobs;
        jobs.j[0] = { (const float4*)x_in, (uint4*)xtf, (M_ENC * DMODEL) / 4 };
        jobs.j[1] = { (const float4*)y_in, (uint4*)ytf, (M_DEC * DMODEL) / 4 };
        conv_multi_kernel<<<dim3(160, 2), 256>>>(jobs, 2);
    }

    // -------- encoder --------
    const float* xc = x_in;
    for (int i = 0; i < 2; i++) {
        mgemm(xtf, eqkvW + (size_t)i * LQKV, nullptr, qkv, M_ENC, NQKV, DMODEL, 0, 1, 1, vtE);
        flash_attn<<<dim3(T_ENC / 128, BHT), 256, FLASH_SMEM>>>(
            qkv, NQKV, qkv + 512, NQKV, vtE, att, T_ENC, T_ENC);
        ln_res_kernel<<<M_ENC, 256>>>(xc, att, enc_ln1_g + i * DMODEL, enc_ln1_b + i * DMODEL, x1, x1tf);
        mgemm(x1tf, ew1 + (size_t)i * FO1, enc_ff_b1 + i * DFF, h, M_ENC, DFF, DMODEL, 1, 1);
        mgemm(h, ew2 + (size_t)i * FO1, enc_ff_b2 + i * DMODEL, att, M_ENC, DMODEL, DFF, 0, 0);
        ln_res_kernel<<<M_ENC, 256>>>(x1, att, enc_ln2_g + i * DMODEL, enc_ln2_b + i * DMODEL, gx, xtf);
        xc = gx;
    }

    // -------- decoder cross K/V for BOTH layers (one full-wave GEMM; V -> vtD d-major) --------
    mgemm(xtf, dkv2, nullptr, kv, M_ENC, NKV2, DMODEL, 0, 1, 2, vtD);

    // -------- decoder --------
    const float* yc = y_in;
    for (int i = 0; i < 2; i++) {
        // masked self-attention: exact fp32 fused path (post-softmax -1e10 fill)
        mgemm(ytf, dqkv1 + (size_t)i * LQKV, nullptr, qkvd, M_DEC, NQKV, DMODEL, 0, 0);
        dec_self_attn<<<BHT, 256, DEC_SMEM>>>(qkvd, att);
        ln_res_kernel<<<M_DEC, 256>>>(yc, att, dec_ln1_g + i * DMODEL, dec_ln1_b + i * DMODEL, y1, y1tf);

        // cross-attention (non-causal -> flash; K/V precomputed, V d-major)
        mgemm(y1tf, dq2 + i * WO, nullptr, qx, M_DEC, DMODEL, DMODEL, 0, 1);
        flash_attn<<<dim3(1, BHT), 256, FLASH_SMEM>>>(
            qx, DMODEL, kv + (size_t)i * 1024, NKV2,
            vtD + (size_t)i * BHT * DHEAD * T_ENC, att, T_DEC, T_ENC);
        ln_res_kernel<<<M_DEC, 256>>>(y1, att, dec_ln2_g + i * DMODEL, dec_ln2_b + i * DMODEL, y2, y2tf);

        // feed-forward
        mgemm(y2tf, dw1 + (size_t)i * FO1, dec_ff_b1 + i * DFF, h, M_DEC, DFF, DMODEL, 1, 1);
        mgemm(h, dw2 + (size_t)i * FO1, dec_ff_b2 + i * DMODEL, att, M_DEC, DMODEL, DFF, 0, 0);
        float* outp = (i == 1) ? (float*)d_out : gy;
        ln_res_kernel<<<M_DEC, 256>>>(y2, att, dec_ln3_g + i * DMODEL, dec_ln3_b + i * DMODEL,
                                      outp, (i == 1) ? nullptr : ytf);
        yc = gy;
    }
}

// round 17
// speedup vs baseline: 1.1864x; 1.0547x over previous
#include <cuda_runtime.h>
#include <cstdint>
#include <cstddef>

// ---------------- problem constants ----------------
#define BATCH   8
#define T_ENC   1024
#define T_DEC   100
#define DMODEL  512
#define NHEAD   8
#define DHEAD   64
#define DFF     2048
#define M_ENC   (BATCH * T_ENC)   // 8192
#define M_DEC   (BATCH * T_DEC)   // 800
#define BHT     (BATCH * NHEAD)   // 64
#define NQKV    1536
#define NKV2    2048              // both decoder layers' K|V fused along N

// ---------------- fused tf32 weights, TRANSPOSED [N][K] ----------------
__device__ uint32_t w_eqkv[2 * NQKV * DMODEL];
__device__ uint32_t w_ew1 [2 * DFF * DMODEL];
__device__ uint32_t w_ew2 [2 * DMODEL * DFF];
__device__ uint32_t w_dqkv1[2 * NQKV * DMODEL];
__device__ uint32_t w_dq2 [2 * DMODEL * DMODEL];
__device__ uint32_t w_dkv2[NKV2 * DMODEL];
__device__ uint32_t w_dw1 [2 * DFF * DMODEL];
__device__ uint32_t w_dw2 [2 * DMODEL * DFF];

// ---------------- activations / scratch ----------------
__device__ uint32_t g_qkv [M_ENC * NQKV];        // enc Q|K (tf32); V region unused
__device__ float    g_qkvd[M_DEC * NQKV];        // dec self QKV (fp32 exact)
__device__ uint32_t g_kv  [M_ENC * NKV2];        // dec cross K both layers; V regions unused
__device__ uint32_t g_vtE [BHT * DHEAD * T_ENC]; // enc V, d-major [bh][64][1024]
__device__ uint32_t g_vtD [2 * BHT * DHEAD * T_ENC]; // dec cross V, per layer
__device__ uint32_t g_qx  [M_DEC * DMODEL];
__device__ uint32_t g_h   [M_ENC * DFF];
__device__ uint32_t g_xtf [M_ENC * DMODEL];
__device__ uint32_t g_x1tf[M_ENC * DMODEL];
__device__ uint32_t g_ytf [M_DEC * DMODEL];
__device__ uint32_t g_y1tf[M_DEC * DMODEL];
__device__ uint32_t g_y2tf[M_DEC * DMODEL];
__device__ float g_att [M_ENC * DMODEL];         // encoder attention/FFN scratch
__device__ float g_attD[M_DEC * DMODEL];         // decoder attention/FFN scratch
__device__ float g_x1  [M_ENC * DMODEL];
__device__ float g_x   [M_ENC * DMODEL];
__device__ float g_y1  [M_DEC * DMODEL];
__device__ float g_y2  [M_DEC * DMODEL];
__device__ float g_y   [M_DEC * DMODEL];

__device__ __forceinline__ uint32_t f2tf32(float x) {
    uint32_t t;
    asm("cvt.rna.tf32.f32 %0, %1;" : "=r"(t) : "f"(x));
    return t;
}

__device__ __forceinline__ void mma8(float* c, const uint32_t* a, uint32_t b0, uint32_t b1) {
    asm volatile(
        "mma.sync.aligned.m16n8k8.row.col.f32.tf32.tf32.f32 "
        "{%0,%1,%2,%3}, {%4,%5,%6,%7}, {%8,%9}, {%0,%1,%2,%3};"
        : "+f"(c[0]), "+f"(c[1]), "+f"(c[2]), "+f"(c[3])
        : "r"(a[0]), "r"(a[1]), "r"(a[2]), "r"(a[3]), "r"(b0), "r"(b1));
}

__device__ __forceinline__ void ldsm4(uint32_t& r0, uint32_t& r1, uint32_t& r2, uint32_t& r3,
                                      uint32_t addr) {
    asm volatile("ldmatrix.sync.aligned.m8n8.x4.shared.b16 {%0,%1,%2,%3}, [%4];"
                 : "=r"(r0), "=r"(r1), "=r"(r2), "=r"(r3) : "r"(addr));
}

__device__ __forceinline__ void cpasync16(uint32_t smem_dst, const void* gsrc, int bytes) {
    asm volatile("cp.async.ca.shared.global [%0], [%1], 16, %2;"
                 :: "r"(smem_dst), "l"(gsrc), "r"(bytes));
}

__device__ __forceinline__ uint4 cvt4(float4 v) {
    return make_uint4(f2tf32(v.x), f2tf32(v.y), f2tf32(v.z), f2tf32(v.w));
}

// ---------------- transpose-convert packing: src [K][N] fp32 -> dst [N][K] tf32 ----------------
struct TJob { const float* src; uint32_t* dst; int K; int N; float scale; };
struct TJobs { TJob j[26]; };

__global__ void tpack_kernel(TJobs jobs, int njobs) {
    const int job = blockIdx.z;
    if (job >= njobs) return;
    const TJob jb = jobs.j[job];
    const int nt = blockIdx.x << 5, kt = blockIdx.y << 5;
    if (nt >= jb.N || kt >= jb.K) return;
    __shared__ float tile[32][33];
    const int tx = threadIdx.x & 31, ty = threadIdx.x >> 5;
    #pragma unroll
    for (int i = 0; i < 4; i++) {
        int k = kt + ty + i * 8;
        tile[ty + i * 8][tx] = jb.src[(size_t)k * jb.N + nt + tx];
    }
    __syncthreads();
    #pragma unroll
    for (int i = 0; i < 4; i++) {
        int n = nt + ty + i * 8;
        jb.dst[(size_t)n * jb.K + kt + tx] = f2tf32(tile[tx][ty + i * 8] * jb.scale);
    }
}

// ---------------- plain conversion (x / y inputs) ----------------
struct ConvJob { const float4* src; uint4* dst; int n4; };
struct ConvJobs { ConvJob j[2]; };

__global__ void conv_multi_kernel(ConvJobs jobs, int njobs) {
    int seg = blockIdx.y;
    if (seg >= njobs) return;
    ConvJob jb = jobs.j[seg];
    for (int i = blockIdx.x * blockDim.x + threadIdx.x; i < jb.n4; i += gridDim.x * blockDim.x) {
        jb.dst[i] = cvt4(jb.src[i]);
    }
}

// ================= 2-stage cp.async tf32 GEMM (ldmatrix A+B; V-transpose epilogue) =================
// R14 proven configuration: 72KB smem, 2 CTAs/SM.
#define GA_STRIDE 36
#define GA_STAGE  (128 * GA_STRIDE)
#define GB_STAGE  (128 * GA_STRIDE)
#define GEMM_SMEM ((2 * GA_STAGE + 2 * GB_STAGE) * 4)

template<int RELU, int TF32OUT>
__global__ __launch_bounds__(256)
void mma_gemm(const uint32_t* __restrict__ A, const uint32_t* __restrict__ B,
              const float* __restrict__ bias, void* __restrict__ Cv,
              int M, int N, int K, int vmode, uint32_t* __restrict__ vt)
{
    extern __shared__ uint32_t gsm[];
    uint32_t* Asf = gsm;
    uint32_t* Bsf = gsm + 2 * GA_STAGE;

    const int tid  = threadIdx.x;
    const int wid  = tid >> 5, lane = tid & 31;
    const int wm   = wid & 1, wn = wid >> 1;
    const int g    = lane >> 2, tig = lane & 3;
    const int m0   = blockIdx.y * 128, n0 = blockIdx.x * 128;

    const int lt = lane >> 3, lr = lane & 7;
    const int a_row = lr + ((lt & 1) << 3);
    const int a_col = (lt >> 1) << 2;
    const int b_row = lr + ((lt >> 1) << 3);
    const int b_col = (lt & 1) << 2;

    const uint32_t aBase = (uint32_t)__cvta_generic_to_shared(Asf);
    const uint32_t bBase = (uint32_t)__cvta_generic_to_shared(Bsf);

    float acc[4][4][4];
    #pragma unroll
    for (int i = 0; i < 4; i++)
        #pragma unroll
        for (int j = 0; j < 4; j++)
            #pragma unroll
            for (int c = 0; c < 4; c++) acc[i][j][c] = 0.f;

    auto issue = [&](int s, int k0) {
        #pragma unroll
        for (int i = 0; i < 4; i++) {
            int idx = tid + (i << 8);
            int r = idx >> 3, kk4 = (idx & 7) << 2;
            int m = m0 + r;
            const uint32_t* src = A + (size_t)(m < M ? m : 0) * K + k0 + kk4;
            cpasync16(aBase + (s * GA_STAGE + r * GA_STRIDE + kk4) * 4, src, (m < M) ? 16 : 0);
        }
        #pragma unroll
        for (int i = 0; i < 4; i++) {
            int idx = tid + (i << 8);
            int r = idx >> 3, kk4 = (idx & 7) << 2;
            const uint32_t* src = B + (size_t)(n0 + r) * K + k0 + kk4;
            cpasync16(bBase + (s * GB_STAGE + r * GA_STRIDE + kk4) * 4, src, 16);
        }
        asm volatile("cp.async.commit_group;");
    };

    const int nk = K >> 5;
    issue(0, 0);

    for (int kt = 0; kt < nk; kt++) {
        const int s = kt & 1;
        if (kt + 1 < nk) {
            issue(s ^ 1, (kt + 1) << 5);
            asm volatile("cp.async.wait_group 1;");
        } else {
            asm volatile("cp.async.wait_group 0;");
        }
        __syncthreads();

        const uint32_t aLane = aBase +
            (s * GA_STAGE + (wm * 64 + a_row) * GA_STRIDE + a_col) * 4;
        const uint32_t bLane = bBase +
            (s * GB_STAGE + (wn * 32 + b_row) * GA_STRIDE + b_col) * 4;
        #pragma unroll
        for (int ks = 0; ks < 32; ks += 8) {
            uint32_t af[4][4];
            #pragma unroll
            for (int mi = 0; mi < 4; mi++)
                ldsm4(af[mi][0], af[mi][1], af[mi][2], af[mi][3],
                      aLane + (mi * 16 * GA_STRIDE + ks) * 4);
            uint32_t bf[4][2];
            ldsm4(bf[0][0], bf[0][1], bf[1][0], bf[1][1], bLane + ks * 4);
            ldsm4(bf[2][0], bf[2][1], bf[3][0], bf[3][1],
                  bLane + (16 * GA_STRIDE + ks) * 4);
            #pragma unroll
            for (int mi = 0; mi < 4; mi++)
                #pragma unroll
                for (int ni = 0; ni < 4; ni++)
                    mma8(acc[mi][ni], af[mi], bf[ni][0], bf[ni][1]);
        }
        __syncthreads();
    }

    // ---- epilogue ----
    bool vtile = false;
    int vrow0 = 0;
    if (TF32OUT && vmode) {
        if (vmode == 1 && n0 >= 1024) {
            vtile = true;
            vrow0 = (m0 >> 10) * 512 + (n0 - 1024);
        } else if (vmode == 2 && (n0 & 512)) {
            vtile = true;
            vrow0 = (n0 >> 10) * 4096 + (m0 >> 10) * 512 + ((n0 & 1023) - 512);
        }
    }

    if (!vtile) {
        #pragma unroll
        for (int mi = 0; mi < 4; mi++) {
            int mb = m0 + wm * 64 + mi * 16;
            #pragma unroll
            for (int ni = 0; ni < 4; ni++) {
                int nb = n0 + wn * 32 + ni * 8 + 2 * tig;
                #pragma unroll
                for (int half = 0; half < 2; half++) {
                    int m = mb + g + half * 8;
                    if (m < M) {
                        float v0 = acc[mi][ni][half * 2    ];
                        float v1 = acc[mi][ni][half * 2 + 1];
                        if (bias) { v0 += bias[nb]; v1 += bias[nb + 1]; }
                        if (RELU) { v0 = fmaxf(v0, 0.f); v1 = fmaxf(v1, 0.f); }
                        if (TF32OUT) {
                            *(uint2*)((uint32_t*)Cv + (size_t)m * N + nb) =
                                make_uint2(f2tf32(v0), f2tf32(v1));
                        } else {
                            *(float2*)((float*)Cv + (size_t)m * N + nb) = make_float2(v0, v1);
                        }
                    }
                }
            }
        }
    } else {
        uint32_t* st = gsm;   // 128 x 132 (<= GEMM smem)
        #pragma unroll
        for (int mi = 0; mi < 4; mi++) {
            int mloc = wm * 64 + mi * 16 + g;
            #pragma unroll
            for (int ni = 0; ni < 4; ni++) {
                int nloc = wn * 32 + ni * 8 + 2 * tig;
                st[(nloc    ) * 132 + mloc    ] = f2tf32(acc[mi][ni][0]);
                st[(nloc + 1) * 132 + mloc    ] = f2tf32(acc[mi][ni][1]);
                st[(nloc    ) * 132 + mloc + 8] = f2tf32(acc[mi][ni][2]);
                st[(nloc + 1) * 132 + mloc + 8] = f2tf32(acc[mi][ni][3]);
            }
        }
        __syncthreads();
        const int tok0 = m0 & 1023;
        #pragma unroll
        for (int it = 0; it < 16; it++) {
            int idx = tid + (it << 8);
            int r = idx >> 5, ch = (idx & 31) << 2;
            uint4 v = *(uint4*)&st[r * 132 + ch];
            *(uint4*)(vt + (size_t)(vrow0 + r) * 1024 + tok0 + ch) = v;
        }
    }
}

// ================= fused flash attention (non-causal, exact) — R12 proven =================
#define FQ_STRIDE 68
#define FKV_STAGE (64 * FQ_STRIDE)
#define FLASH_SMEM ((4 * FKV_STAGE) * 4)

__global__ __launch_bounds__(256, 2)
void flash_attn(const uint32_t* __restrict__ Qg, int ldq,
                const uint32_t* __restrict__ Kg, int ldkv,
                const uint32_t* __restrict__ Vt,
                float* __restrict__ Og, int Tq, int Tk)
{
    extern __shared__ uint32_t fsm[];
    uint32_t* Kraw = fsm;                    // 2 x [64][68]
    uint32_t* Vraw = fsm + 2 * FKV_STAGE;    // 2 x [64][68]

    const int bh = blockIdx.y;
    const int b = bh >> 3, h = bh & 7;
    const int q0 = blockIdx.x * 128;
    const int tid = threadIdx.x;
    const int wid = tid >> 5, lane = tid & 31;
    const int g = lane >> 2, tig = lane & 3;
    const int mr = wid * 16;

    const int lt = lane >> 3, lr = lane & 7;
    const int a_row = lr + ((lt & 1) << 3);
    const int a_col = (lt >> 1) << 2;
    const int k_row = lr + ((lt >> 1) << 3);
    const int k_col = (lt & 1) << 2;

    const uint32_t* qp = Qg + (size_t)b * Tq * ldq + h * DHEAD;
    const uint32_t* kp = Kg + (size_t)b * Tk * ldkv + h * DHEAD;
    const uint32_t* vp = Vt + (size_t)bh * 64 * Tk;

    const uint32_t kBase = (uint32_t)__cvta_generic_to_shared(Kraw);
    const uint32_t vBase = (uint32_t)__cvta_generic_to_shared(Vraw);

    // ---- stage Q (128 x 64) through the 128-row K+V buffer space, hoist to regs ----
    #pragma unroll
    for (int i = 0; i < 8; i++) {
        int idx = tid + (i << 8);
        int r = idx >> 4, d4 = (idx & 15) << 2;
        int q = q0 + r;
        cpasync16(kBase + (r * FQ_STRIDE + d4) * 4,
                  qp + (size_t)(q < Tq ? q : 0) * ldq + d4, 16);
    }
    asm volatile("cp.async.commit_group;");
    asm volatile("cp.async.wait_group 0;");
    __syncthreads();
    uint32_t qf[8][4];
    {
        const uint32_t qLane = kBase + ((mr + a_row) * FQ_STRIDE + a_col) * 4;
        #pragma unroll
        for (int j = 0; j < 8; j++)
            ldsm4(qf[j][0], qf[j][1], qf[j][2], qf[j][3], qLane + (j << 5));
    }
    __syncthreads();   // all warps done reading Q before KV overwrites the buffer

    auto issueKV = [&](int s, int kt) {
        #pragma unroll
        for (int i = 0; i < 4; i++) {
            int idx = tid + (i << 8);
            int r = idx >> 4, d4 = (idx & 15) << 2;
            cpasync16(kBase + (s * FKV_STAGE + r * FQ_STRIDE + d4) * 4,
                      kp + (size_t)(kt + r) * ldkv + d4, 16);
            cpasync16(vBase + (s * FKV_STAGE + r * FQ_STRIDE + d4) * 4,
                      vp + (size_t)r * Tk + kt + d4, 16);
        }
        asm volatile("cp.async.commit_group;");
    };

    issueKV(0, 0);

    float o[8][4];
    #pragma unroll
    for (int ni = 0; ni < 8; ni++)
        #pragma unroll
        for (int c = 0; c < 4; c++) o[ni][c] = 0.f;
    float m0 = -1e30f, m1 = -1e30f, l0 = 0.f, l1 = 0.f;

    const int srcA = (lane & ~3) | (tig >> 1);
    const int srcB = srcA + 2;
    const bool odd = tig & 1;

    const int nt = Tk >> 6;
    for (int kt = 0; kt < nt; kt++) {
        const int s = kt & 1;
        if (kt + 1 < nt) {
            issueKV(s ^ 1, (kt + 1) << 6);
            asm volatile("cp.async.wait_group 1;");
        } else {
            asm volatile("cp.async.wait_group 0;");
        }
        __syncthreads();

        const uint32_t kLane = kBase + (s * FKV_STAGE + k_row * FQ_STRIDE + k_col) * 4;
        const uint32_t vLane = vBase + (s * FKV_STAGE + k_row * FQ_STRIDE + k_col) * 4;

        // ---- S = Q @ K^T (Q from registers) ----
        float sfr[8][4];
        #pragma unroll
        for (int ni = 0; ni < 8; ni++)
            #pragma unroll
            for (int c = 0; c < 4; c++) sfr[ni][c] = 0.f;
        #pragma unroll
        for (int j = 0; j < 8; j++) {
            const int ks = j * 8;
            #pragma unroll
            for (int np = 0; np < 8; np += 2) {
                uint32_t b00, b01, b10, b11;
                ldsm4(b00, b01, b10, b11, kLane + (np * 8 * FQ_STRIDE + ks) * 4);
                mma8(sfr[np    ], qf[j], b00, b01);
                mma8(sfr[np + 1], qf[j], b10, b11);
            }
        }

        // ---- online softmax; tf32 P bits stored in-place in sfr ----
        float tmax0 = -1e30f, tmax1 = -1e30f;
        #pragma unroll
        for (int ni = 0; ni < 8; ni++) {
            tmax0 = fmaxf(tmax0, fmaxf(sfr[ni][0], sfr[ni][1]));
            tmax1 = fmaxf(tmax1, fmaxf(sfr[ni][2], sfr[ni][3]));
        }
        #pragma unroll
        for (int off = 1; off <= 2; off <<= 1) {
            tmax0 = fmaxf(tmax0, __shfl_xor_sync(0xffffffffu, tmax0, off));
            tmax1 = fmaxf(tmax1, __shfl_xor_sync(0xffffffffu, tmax1, off));
        }
        const float mn0 = fmaxf(m0, tmax0), mn1 = fmaxf(m1, tmax1);
        const float a0 = __expf(m0 - mn0), a1 = __expf(m1 - mn1);
        float rs0 = 0.f, rs1 = 0.f;
        #pragma unroll
        for (int ni = 0; ni < 8; ni++) {
            float p0 = __expf(sfr[ni][0] - mn0);
            float p1 = __expf(sfr[ni][1] - mn0);
            float p2 = __expf(sfr[ni][2] - mn1);
            float p3 = __expf(sfr[ni][3] - mn1);
            rs0 += p0 + p1; rs1 += p2 + p3;
            sfr[ni][0] = __uint_as_float(f2tf32(p0));
            sfr[ni][1] = __uint_as_float(f2tf32(p1));
            sfr[ni][2] = __uint_as_float(f2tf32(p2));
            sfr[ni][3] = __uint_as_float(f2tf32(p3));
        }
        #pragma unroll
        for (int off = 1; off <= 2; off <<= 1) {
            rs0 += __shfl_xor_sync(0xffffffffu, rs0, off);
            rs1 += __shfl_xor_sync(0xffffffffu, rs1, off);
        }
        l0 = l0 * a0 + rs0; l1 = l1 * a1 + rs1;
        m0 = mn0; m1 = mn1;
        #pragma unroll
        for (int ni = 0; ni < 8; ni++) {
            o[ni][0] *= a0; o[ni][1] *= a0;
            o[ni][2] *= a1; o[ni][3] *= a1;
        }

        // ---- O += P @ V : P c-frag -> a-frag via quad shuffles; V via ldmatrix ----
        #pragma unroll
        for (int j = 0; j < 8; j++) {
            uint32_t p0 = __float_as_uint(sfr[j][0]);
            uint32_t p1 = __float_as_uint(sfr[j][1]);
            uint32_t p2 = __float_as_uint(sfr[j][2]);
            uint32_t p3 = __float_as_uint(sfr[j][3]);
            uint32_t r0a = __shfl_sync(0xffffffffu, p0, srcA);
            uint32_t r1a = __shfl_sync(0xffffffffu, p1, srcA);
            uint32_t r2a = __shfl_sync(0xffffffffu, p2, srcA);
            uint32_t r3a = __shfl_sync(0xffffffffu, p3, srcA);
            uint32_t r0b = __shfl_sync(0xffffffffu, p0, srcB);
            uint32_t r1b = __shfl_sync(0xffffffffu, p1, srcB);
            uint32_t r2b = __shfl_sync(0xffffffffu, p2, srcB);
            uint32_t r3b = __shfl_sync(0xffffffffu, p3, srcB);
            uint32_t af[4];
            af[0] = odd ? r1a : r0a;
            af[1] = odd ? r3a : r2a;
            af[2] = odd ? r1b : r0b;
            af[3] = odd ? r3b : r2b;
            const int ks = j * 8;
            #pragma unroll
            for (int np = 0; np < 8; np += 2) {
                uint32_t b00, b01, b10, b11;
                ldsm4(b00, b01, b10, b11, vLane + (np * 8 * FQ_STRIDE + ks) * 4);
                mma8(o[np    ], af, b00, b01);
                mma8(o[np + 1], af, b10, b11);
            }
        }
        __syncthreads();
    }

    const float i0 = 1.f / l0, i1 = 1.f / l1;
    #pragma unroll
    for (int ni = 0; ni < 8; ni++) {
        int col = h * DHEAD + ni * 8 + 2 * tig;
        int r0 = q0 + mr + g, r1 = r0 + 8;
        if (r0 < Tq)
            *(float2*)(Og + (size_t)(b * Tq + r0) * DMODEL + col) =
                make_float2(o[ni][0] * i0, o[ni][1] * i0);
        if (r1 < Tq)
            *(float2*)(Og + (size_t)(b * Tq + r1) * DMODEL + col) =
                make_float2(o[ni][2] * i1, o[ni][3] * i1);
    }
}

// ================= fused decoder self-attention (exact fp32) =================
#define DS_STRIDE 68
#define DS_SSTRIDE 104
#define DEC_SMEM ((3 * T_DEC * DS_STRIDE + T_DEC * DS_SSTRIDE) * 4)

__global__ __launch_bounds__(256)
void dec_self_attn(const float* __restrict__ QKV, float* __restrict__ Og)
{
    extern __shared__ float dsm[];
    float* Qd = dsm;
    float* Kd = Qd + T_DEC * DS_STRIDE;
    float* Vd = Kd + T_DEC * DS_STRIDE;
    float* Sd = Vd + T_DEC * DS_STRIDE;

    const int bh = blockIdx.x;
    const int b = bh >> 3, h = bh & 7;
    const int tid = threadIdx.x;
    const int wid = tid >> 5, lane = tid & 31;

    const float* qp = QKV + (size_t)b * T_DEC * NQKV + h * DHEAD;
    const float* kp = qp + 512;
    const float* vp = qp + 1024;

    for (int idx = tid; idx < T_DEC * 16; idx += 256) {
        int r = idx >> 4, d4 = (idx & 15) << 2;
        *(float4*)&Qd[r * DS_STRIDE + d4] = *(const float4*)(qp + (size_t)r * NQKV + d4);
        *(float4*)&Kd[r * DS_STRIDE + d4] = *(const float4*)(kp + (size_t)r * NQKV + d4);
        *(float4*)&Vd[r * DS_STRIDE + d4] = *(const float4*)(vp + (size_t)r * NQKV + d4);
    }
    __syncthreads();

    for (int e = tid; e < T_DEC * T_DEC; e += 256) {
        int q = e / T_DEC, kk = e - q * T_DEC;
        const float* qr = &Qd[q * DS_STRIDE];
        const float* kr = &Kd[kk * DS_STRIDE];
        float acc = 0.f;
        #pragma unroll
        for (int d = 0; d < 64; d++) acc += qr[d] * kr[d];
        Sd[q * DS_SSTRIDE + kk] = acc * 0.125f;
    }
    __syncthreads();

    for (int q = wid; q < T_DEC; q += 8) {
        float* row = &Sd[q * DS_SSTRIDE];
        float r0 = (lane      < T_DEC) ? row[lane]      : -1e30f;
        float r1 = (lane + 32 < T_DEC) ? row[lane + 32] : -1e30f;
        float r2 = (lane + 64 < T_DEC) ? row[lane + 64] : -1e30f;
        float r3 = (lane + 96 < T_DEC) ? row[lane + 96] : -1e30f;
        float m = fmaxf(fmaxf(r0, r1), fmaxf(r2, r3));
        #pragma unroll
        for (int off = 16; off; off >>= 1) m = fmaxf(m, __shfl_xor_sync(0xffffffffu, m, off));
        float e0 = expf(r0 - m), e1 = expf(r1 - m), e2 = expf(r2 - m), e3 = expf(r3 - m);
        if (lane      >= T_DEC) e0 = 0.f;
        if (lane + 32 >= T_DEC) e1 = 0.f;
        if (lane + 64 >= T_DEC) e2 = 0.f;
        if (lane + 96 >= T_DEC) e3 = 0.f;
        float s = e0 + e1 + e2 + e3;
        #pragma unroll
        for (int off = 16; off; off >>= 1) s += __shfl_xor_sync(0xffffffffu, s, off);
        const float inv = 1.f / s;
        if (lane      < T_DEC) row[lane]      = (lane      > q) ? -1e10f : e0 * inv;
        if (lane + 32 < T_DEC) row[lane + 32] = (lane + 32 > q) ? -1e10f : e1 * inv;
        if (lane + 64 < T_DEC) row[lane + 64] = (lane + 64 > q) ? -1e10f : e2 * inv;
        if (lane + 96 < T_DEC) row[lane + 96] = (lane + 96 > q) ? -1e10f : e3 * inv;
    }
    __syncthreads();

    for (int e = tid; e < T_DEC * 64; e += 256) {
        int q = e >> 6, d = e & 63;
        const float* pr = &Sd[q * DS_SSTRIDE];
        float acc = 0.f;
        #pragma unroll 4
        for (int kk = 0; kk < T_DEC; kk++) acc += pr[kk] * Vd[kk * DS_STRIDE + d];
        Og[(size_t)(b * T_DEC + q) * DMODEL + h * DHEAD + d] = acc;
    }
}

// ---------------- fused residual + LayerNorm: 1 barrier, vectorized (float2) ----------------
__global__ void ln_res_kernel(const float* __restrict__ A, const float* __restrict__ Bv,
                              const float* __restrict__ g, const float* __restrict__ be,
                              float* __restrict__ O, uint32_t* __restrict__ Otf) {
    const int row = blockIdx.x;
    const float* a = A + (size_t)row * DMODEL;
    const float* b = Bv + (size_t)row * DMODEL;
    __shared__ float red[16];
    const int tid = threadIdx.x;
    const int lane = tid & 31, warp = tid >> 5;
    const int e0i = tid << 1;

    const float2 av = *(const float2*)(a + e0i);
    const float2 bv = *(const float2*)(b + e0i);
    const float v0 = av.x + bv.x;
    const float v1 = av.y + bv.y;

    float s  = v0 + v1;
    float sq = v0 * v0 + v1 * v1;
    #pragma unroll
    for (int off = 16; off; off >>= 1) {
        s  += __shfl_xor_sync(0xffffffffu, s,  off);
        sq += __shfl_xor_sync(0xffffffffu, sq, off);
    }
    if (lane == 0) { red[warp] = s; red[warp + 8] = sq; }
    __syncthreads();
    s = red[0] + red[1] + red[2] + red[3] + red[4] + red[5] + red[6] + red[7];
    sq = red[8] + red[9] + red[10] + red[11] + red[12] + red[13] + red[14] + red[15];

    const float mean = s * (1.f / DMODEL);
    const float var  = fmaxf(sq * (1.f / DMODEL) - mean * mean, 0.f);
    const float inv  = rsqrtf(var + 1e-5f);

    const float2 gv = *(const float2*)(g + e0i);
    const float2 bev = *(const float2*)(be + e0i);
    const float o0 = (v0 - mean) * inv * gv.x + bev.x;
    const float o1 = (v1 - mean) * inv * gv.y + bev.y;
    *(float2*)(O + (size_t)row * DMODEL + e0i) = make_float2(o0, o1);
    if (Otf) {
        *(uint2*)(Otf + (size_t)row * DMODEL + e0i) = make_uint2(f2tf32(o0), f2tf32(o1));
    }
}

// ---------------- host orchestration ----------------
static inline void mgemm(const uint32_t* A, const uint32_t* B, const float* bias, void* C,
                         int M, int N, int K, int relu, int tf32out,
                         int vmode = 0, uint32_t* vt = nullptr, cudaStream_t st = 0) {
    dim3 grid(N / 128, (M + 127) / 128);
    if (relu && tf32out)
        mma_gemm<1, 1><<<grid, 256, GEMM_SMEM, st>>>(A, B, bias, C, M, N, K, vmode, vt);
    else if (tf32out)
        mma_gemm<0, 1><<<grid, 256, GEMM_SMEM, st>>>(A, B, bias, C, M, N, K, vmode, vt);
    else
        mma_gemm<0, 0><<<grid, 256, GEMM_SMEM, st>>>(A, B, bias, C, M, N, K, vmode, vt);
}

template <typename T>
static inline void* symv(T& s) {
    void* p = nullptr;
    cudaGetSymbolAddress(&p, s);
    return p;
}

// side stream / events: created once on the (uncaptured) correctness call;
// reused identically on every call -> deterministic captured graph.
static cudaStream_t g_side = nullptr;
static cudaEvent_t  g_evFork = nullptr, g_evJoin = nullptr;

extern "C" void kernel_launch(void* const* d_in, const int* in_sizes, int n_in,
                              void* d_out, int out_size) {
    (void)in_sizes; (void)n_in; (void)out_size;

    if (!g_side) {
        cudaStreamCreateWithFlags(&g_side, cudaStreamNonBlocking);
        cudaEventCreateWithFlags(&g_evFork, cudaEventDisableTiming);
        cudaEventCreateWithFlags(&g_evJoin, cudaEventDisableTiming);
        cudaFuncSetAttribute((const void*)mma_gemm<0,0>, cudaFuncAttributeMaxDynamicSharedMemorySize, GEMM_SMEM);
        cudaFuncSetAttribute((const void*)mma_gemm<0,1>, cudaFuncAttributeMaxDynamicSharedMemorySize, GEMM_SMEM);
        cudaFuncSetAttribute((const void*)mma_gemm<1,1>, cudaFuncAttributeMaxDynamicSharedMemorySize, GEMM_SMEM);
        cudaFuncSetAttribute((const void*)flash_attn,    cudaFuncAttributeMaxDynamicSharedMemorySize, FLASH_SMEM);
        cudaFuncSetAttribute((const void*)dec_self_attn, cudaFuncAttributeMaxDynamicSharedMemorySize, DEC_SMEM);
    }

    const float* x_in      = (const float*)d_in[0];
    const float* y_in      = (const float*)d_in[1];
    const float* enc_Wq    = (const float*)d_in[2];
    const float* enc_Wk    = (const float*)d_in[3];
    const float* enc_Wv    = (const float*)d_in[4];
    const float* enc_ff_w1 = (const float*)d_in[5];
    const float* enc_ff_b1 = (const float*)d_in[6];
    const float* enc_ff_w2 = (const float*)d_in[7];
    const float* enc_ff_b2 = (const float*)d_in[8];
    const float* enc_ln1_g = (const float*)d_in[9];
    const float* enc_ln1_b = (const float*)d_in[10];
    const float* enc_ln2_g = (const float*)d_in[11];
    const float* enc_ln2_b = (const float*)d_in[12];
    const float* dec_Wq1   = (const float*)d_in[13];
    const float* dec_Wk1   = (const float*)d_in[14];
    const float* dec_Wv1   = (const float*)d_in[15];
    const float* dec_Wq2   = (const float*)d_in[16];
    const float* dec_Wk2   = (const float*)d_in[17];
    const float* dec_Wv2   = (const float*)d_in[18];
    const float* dec_ff_w1 = (const float*)d_in[19];
    const float* dec_ff_b1 = (const float*)d_in[20];
    const float* dec_ff_w2 = (const float*)d_in[21];
    const float* dec_ff_b2 = (const float*)d_in[22];
    const float* dec_ln1_g = (const float*)d_in[23];
    const float* dec_ln1_b = (const float*)d_in[24];
    const float* dec_ln2_g = (const float*)d_in[25];
    const float* dec_ln2_b = (const float*)d_in[26];
    const float* dec_ln3_g = (const float*)d_in[27];
    const float* dec_ln3_b = (const float*)d_in[28];

    uint32_t* eqkvW = (uint32_t*)symv(w_eqkv);
    uint32_t* ew1   = (uint32_t*)symv(w_ew1);
    uint32_t* ew2   = (uint32_t*)symv(w_ew2);
    uint32_t* dqkv1 = (uint32_t*)symv(w_dqkv1);
    uint32_t* dq2   = (uint32_t*)symv(w_dq2);
    uint32_t* dkv2  = (uint32_t*)symv(w_dkv2);
    uint32_t* dw1   = (uint32_t*)symv(w_dw1);
    uint32_t* dw2   = (uint32_t*)symv(w_dw2);

    uint32_t* qkv  = (uint32_t*)symv(g_qkv);
    float*    qkvd = (float*)symv(g_qkvd);
    uint32_t* kv   = (uint32_t*)symv(g_kv);
    uint32_t* vtE  = (uint32_t*)symv(g_vtE);
    uint32_t* vtD  = (uint32_t*)symv(g_vtD);
    uint32_t* qx   = (uint32_t*)symv(g_qx);
    uint32_t* h    = (uint32_t*)symv(g_h);
    uint32_t* xtf  = (uint32_t*)symv(g_xtf);
    uint32_t* x1tf = (uint32_t*)symv(g_x1tf);
    uint32_t* ytf  = (uint32_t*)symv(g_ytf);
    uint32_t* y1tf = (uint32_t*)symv(g_y1tf);
    uint32_t* y2tf = (uint32_t*)symv(g_y2tf);
    float* att  = (float*)symv(g_att);
    float* attD = (float*)symv(g_attD);
    float* x1  = (float*)symv(g_x1);
    float* gx  = (float*)symv(g_x);
    float* y1  = (float*)symv(g_y1);
    float* y2  = (float*)symv(g_y2);
    float* gy  = (float*)symv(g_y);

    const long long WO = DMODEL * DMODEL;
    const long long FO1 = DFF * DMODEL;
    const long long LQKV = (long long)NQKV * DMODEL;

    // ---- transpose-convert ALL weights [K][N] -> [N][K] tf32 ----
    {
        TJobs tj;
        int n = 0;
        for (int i = 0; i < 2; i++) {
            tj.j[n++] = { enc_Wq + i * WO, eqkvW + i * LQKV +      0LL * DMODEL, DMODEL, DMODEL, 0.125f };
            tj.j[n++] = { enc_Wk + i * WO, eqkvW + i * LQKV +    512LL * DMODEL, DMODEL, DMODEL, 1.f };
            tj.j[n++] = { enc_Wv + i * WO, eqkvW + i * LQKV +   1024LL * DMODEL, DMODEL, DMODEL, 1.f };
            tj.j[n++] = { dec_Wq1 + i * WO, dqkv1 + i * LQKV +     0LL * DMODEL, DMODEL, DMODEL, 1.f };
            tj.j[n++] = { dec_Wk1 + i * WO, dqkv1 + i * LQKV +   512LL * DMODEL, DMODEL, DMODEL, 1.f };
            tj.j[n++] = { dec_Wv1 + i * WO, dqkv1 + i * LQKV +  1024LL * DMODEL, DMODEL, DMODEL, 1.f };
            tj.j[n++] = { dec_Wq2 + i * WO, dq2 + i * WO, DMODEL, DMODEL, 0.125f };
            tj.j[n++] = { dec_Wk2 + i * WO, dkv2 + (i * 1024LL      ) * DMODEL, DMODEL, DMODEL, 1.f };
            tj.j[n++] = { dec_Wv2 + i * WO, dkv2 + (i * 1024LL + 512) * DMODEL, DMODEL, DMODEL, 1.f };
            tj.j[n++] = { enc_ff_w1 + i * FO1, ew1 + i * FO1, DMODEL, DFF, 1.f };
            tj.j[n++] = { enc_ff_w2 + i * FO1, ew2 + i * FO1, DFF, DMODEL, 1.f };
            tj.j[n++] = { dec_ff_w1 + i * FO1, dw1 + i * FO1, DMODEL, DFF, 1.f };
            tj.j[n++] = { dec_ff_w2 + i * FO1, dw2 + i * FO1, DFF, DMODEL, 1.f };
        }
        tpack_kernel<<<dim3(64, 64, n), 256>>>(tj, n);
    }
    {
        ConvJobs jobs;
        jobs.j[0] = { (const float4*)x_in, (uint4*)xtf, (M_ENC * DMODEL) / 4 };
        jobs.j[1] = { (const float4*)y_in, (uint4*)ytf, (M_DEC * DMODEL) / 4 };
        conv_multi_kernel<<<dim3(160, 2), 256>>>(jobs, 2);
    }

    // ---- FORK: decoder layer-0 self-attention path depends only on ytf + weights.
    //      Run it on a side stream, hidden under the encoder.
    cudaEventRecord(g_evFork, 0);
    cudaStreamWaitEvent(g_side, g_evFork, 0);
    mgemm(ytf, dqkv1, nullptr, qkvd, M_DEC, NQKV, DMODEL, 0, 0, 0, nullptr, g_side);
    dec_self_attn<<<BHT, 256, DEC_SMEM, g_side>>>(qkvd, attD);
    ln_res_kernel<<<M_DEC, 256, 0, g_side>>>(y_in, attD, dec_ln1_g, dec_ln1_b, y1, y1tf);
    mgemm(y1tf, dq2, nullptr, qx, M_DEC, DMODEL, DMODEL, 0, 1, 0, nullptr, g_side);
    cudaEventRecord(g_evJoin, g_side);

    // -------- encoder (default stream, concurrent with side work) --------
    const float* xc = x_in;
    for (int i = 0; i < 2; i++) {
        mgemm(xtf, eqkvW + (size_t)i * LQKV, nullptr, qkv, M_ENC, NQKV, DMODEL, 0, 1, 1, vtE);
        flash_attn<<<dim3(T_ENC / 128, BHT), 256, FLASH_SMEM>>>(
            qkv, NQKV, qkv + 512, NQKV, vtE, att, T_ENC, T_ENC);
        ln_res_kernel<<<M_ENC, 256>>>(xc, att, enc_ln1_g + i * DMODEL, enc_ln1_b + i * DMODEL, x1, x1tf);
        mgemm(x1tf, ew1 + (size_t)i * FO1, enc_ff_b1 + i * DFF, h, M_ENC, DFF, DMODEL, 1, 1);
        mgemm(h, ew2 + (size_t)i * FO1, enc_ff_b2 + i * DMODEL, att, M_ENC, DMODEL, DFF, 0, 0);
        ln_res_kernel<<<M_ENC, 256>>>(x1, att, enc_ln2_g + i * DMODEL, enc_ln2_b + i * DMODEL, gx, xtf);
        xc = gx;
    }

    // -------- decoder cross K/V for BOTH layers (one full-wave GEMM; V -> vtD d-major) --------
    mgemm(xtf, dkv2, nullptr, kv, M_ENC, NKV2, DMODEL, 0, 1, 2, vtD);

    // ---- JOIN: L0 self path (qkvd/attD/y1/y1tf/qx) must be complete ----
    cudaStreamWaitEvent(0, g_evJoin, 0);

    // -------- decoder --------
    for (int i = 0; i < 2; i++) {
        if (i == 1) {
            // layer-1 self path (ytf was refreshed by layer-0's ln3)
            mgemm(ytf, dqkv1 + (size_t)LQKV, nullptr, qkvd, M_DEC, NQKV, DMODEL, 0, 0);
            dec_self_attn<<<BHT, 256, DEC_SMEM>>>(qkvd, attD);
            ln_res_kernel<<<M_DEC, 256>>>(gy, attD, dec_ln1_g + DMODEL, dec_ln1_b + DMODEL, y1, y1tf);
            mgemm(y1tf, dq2 + WO, nullptr, qx, M_DEC, DMODEL, DMODEL, 0, 1);
        }

        // cross-attention (non-causal -> flash; K/V precomputed, V d-major)
        flash_attn<<<dim3(1, BHT), 256, FLASH_SMEM>>>(
            qx, DMODEL, kv + (size_t)i * 1024, NKV2,
            vtD + (size_t)i * BHT * DHEAD * T_ENC, attD, T_DEC, T_ENC);
        ln_res_kernel<<<M_DEC, 256>>>(y1, attD, dec_ln2_g + i * DMODEL, dec_ln2_b + i * DMODEL, y2, y2tf);

        // feed-forward
        mgemm(y2tf, dw1 + (size_t)i * FO1, dec_ff_b1 + i * DFF, h, M_DEC, DFF, DMODEL, 1, 1);
        mgemm(h, dw2 + (size_t)i * FO1, dec_ff_b2 + i * DMODEL, attD, M_DEC, DMODEL, DFF, 0, 0);
        float* outp = (i == 1) ? (float*)d_out : gy;
        ln_res_kernel<<<M_DEC, 256>>>(y2, attD, dec_ln3_g + i * DMODEL, dec_ln3_b + i * DMODEL,
                                      outp, (i == 1) ? nullptr : ytf);
    }
}